// round 12
// baseline (speedup 1.0000x reference)
#include <cuda_runtime.h>
#include <cuda_fp16.h>
#include <math.h>
#include <cstdint>

#define NN   512
#define CZ   128
#define NR   (NN*NN)          // 262144
#define EPSV 1e-5f

// ---------------- scratch (device globals; alloc-free) ----------------
__device__ __half g_ah[(size_t)CZ * NR];   // a hi [c][i][k]
__device__ __half g_bh[(size_t)CZ * NR];   // b hi [c][j][k]
__device__ __half g_gate[(size_t)NR * CZ]; // gate[r][c]  (fp16)
__device__ float g_x[(size_t)CZ * NR];     // x[c][i][j]  (fp32)
__device__ __half g_wH[768 * 128];         // packed weights hi [n][k]
__device__ __half g_wL[768 * 128];         // packed weights lo [n][k]

static __device__ __forceinline__ uint32_t smem_u32(const void* p) {
    return (uint32_t)__cvta_generic_to_shared(p);
}
static __device__ __forceinline__ void cp16(uint32_t dst, const void* src) {
    asm volatile("cp.async.cg.shared.global [%0], [%1], 16;" :: "r"(dst), "l"(src));
}
static __device__ __forceinline__ void cp_commit() {
    asm volatile("cp.async.commit_group;" ::: "memory");
}
static __device__ __forceinline__ void cp_wait1() {
    asm volatile("cp.async.wait_group 1;" ::: "memory");
}
static __device__ __forceinline__ void cp_wait0() {
    asm volatile("cp.async.wait_group 0;" ::: "memory");
}
static __device__ __forceinline__ void ldmx4(uint32_t* r, uint32_t addr) {
    asm volatile("ldmatrix.sync.aligned.m8n8.x4.shared.b16 {%0,%1,%2,%3}, [%4];"
                 : "=r"(r[0]), "=r"(r[1]), "=r"(r[2]), "=r"(r[3]) : "r"(addr));
}
static __device__ __forceinline__ void ldmx2(uint32_t* r, uint32_t addr) {
    asm volatile("ldmatrix.sync.aligned.m8n8.x2.shared.b16 {%0,%1}, [%2];"
                 : "=r"(r[0]), "=r"(r[1]) : "r"(addr));
}
static __device__ __forceinline__ void mma16816(float* d, const uint32_t* a, const uint32_t* b) {
    asm volatile("mma.sync.aligned.m16n8k16.row.col.f32.f16.f16.f32 "
                 "{%0,%1,%2,%3}, {%4,%5,%6,%7}, {%8,%9}, {%0,%1,%2,%3};"
                 : "+f"(d[0]), "+f"(d[1]), "+f"(d[2]), "+f"(d[3])
                 : "r"(a[0]), "r"(a[1]), "r"(a[2]), "r"(a[3]), "r"(b[0]), "r"(b[1]));
}

// =====================================================================
// Kernel 0: split weights into fp16 hi/lo, transposed to [n][k].
// n: 0-255 = w_ab_g, 256-511 = w_ab_p, 512-639 = w_g, 640-767 = w_z
// =====================================================================
__global__ void __launch_bounds__(256) k0_wsplit(
    const float* __restrict__ w_ab_g, const float* __restrict__ w_ab_p,
    const float* __restrict__ w_g,   const float* __restrict__ w_z)
{
    int idx = blockIdx.x * 256 + threadIdx.x;   // 384 blocks
    if (idx >= 768 * 128) return;
    int n = idx >> 7, k = idx & 127;
    float v;
    if (n < 256)      v = w_ab_g[k * 256 + n];
    else if (n < 512) v = w_ab_p[k * 256 + (n - 256)];
    else if (n < 640) v = w_g[k * 128 + (n - 512)];
    else              v = w_z[k * 128 + (n - 640)];
    __half h = __float2half(v);
    g_wH[idx] = h;
    g_wL[idx] = __float2half(v - __half2float(h));
}

// =====================================================================
// Kernel 1 (v5): LN(z) + projections, fp16 SINGLE-pass (znH * WH).
// 4096 CTAs x 64 rows, 256 thr (8 warps: 2m x 4n), warp tile 32x16.
// smem 52224 -> reg-limited 2 CTAs/SM; W double-buffered.
// =====================================================================
#define ASTR   136
#define OFF_AH 0                       // 17408 B
#define OFF_WB 17408                   // two 17408-B WH buffers
#define WBSZ   17408
#define K1_SMEM 52224

__global__ void __launch_bounds__(256, 2) k1_mma(
    const float* __restrict__ z, const float* __restrict__ mask,
    const float* __restrict__ b_ab_p, const float* __restrict__ b_ab_g,
    const float* __restrict__ b_g,
    const float* __restrict__ ln_g,  const float* __restrict__ ln_b)
{
    extern __shared__ char smem[];
    const uint32_t sbase = smem_u32(smem);
    const int t   = threadIdx.x;
    const int lid = t & 31;
    const int w   = t >> 5;
    const int wm  = w >> 2;
    const int wn  = w & 3;
    const int r0  = blockIdx.x * 64;

    const int noff[10] = {0, 256, 64, 320, 128, 384, 192, 448, 512, 576};

    // ---- prefetch WH chunk 0 into buffer 0 ----
    {
        #pragma unroll
        for (int p = 0; p < 4; ++p) {
            int idx = p * 256 + t;
            int n = idx >> 4, seg = idx & 15;
            cp16(sbase + OFF_WB + n * 272 + seg * 16,
                 g_wH + (size_t)n * 128 + seg * 8);
        }
        cp_commit();
    }

    // ---- z via LDG -> LN (4 thr/row, shfl) -> fp16 hi smem ----
    {
        const int row = t >> 2, qt = t & 3;
        const float4* zr = (const float4*)(z + (size_t)(r0 + row) * CZ + qt * 32);
        float4 v[8];
        #pragma unroll
        for (int q = 0; q < 8; ++q) v[q] = __ldg(zr + q);
        float s = 0.f, s2 = 0.f;
        #pragma unroll
        for (int q = 0; q < 8; ++q) {
            s  += v[q].x + v[q].y + v[q].z + v[q].w;
            s2 += v[q].x*v[q].x + v[q].y*v[q].y + v[q].z*v[q].z + v[q].w*v[q].w;
        }
        s  += __shfl_xor_sync(0xffffffffu, s, 1);
        s2 += __shfl_xor_sync(0xffffffffu, s2, 1);
        s  += __shfl_xor_sync(0xffffffffu, s, 2);
        s2 += __shfl_xor_sync(0xffffffffu, s2, 2);
        float mu  = s * (1.0f/128.0f);
        float var = fmaxf(s2 * (1.0f/128.0f) - mu*mu, 0.f);
        float rs  = rsqrtf(var + EPSV);

        __half* aH = (__half*)(smem + OFF_AH) + row * ASTR + qt * 32;
        #pragma unroll
        for (int q8 = 0; q8 < 4; ++q8) {
            const float vv[8] = {v[q8*2].x, v[q8*2].y, v[q8*2].z, v[q8*2].w,
                                 v[q8*2+1].x, v[q8*2+1].y, v[q8*2+1].z, v[q8*2+1].w};
            __align__(16) __half hb[8];
            #pragma unroll
            for (int j = 0; j < 8; ++j) {
                int c = qt * 32 + q8 * 8 + j;
                hb[j] = __float2half((vv[j] - mu) * rs * __ldg(ln_g + c) + __ldg(ln_b + c));
            }
            *(uint4*)(aH + q8*8) = *(uint4*)hb;
        }
    }

    const int quad = lid >> 3;
    const int l7   = lid & 7;
    uint32_t aoff[2];
    #pragma unroll
    for (int mf = 0; mf < 2; ++mf) {
        int r = wm*32 + mf*16 + (quad & 1)*8 + l7;
        aoff[mf] = (r * ASTR + (quad >> 1) * 8) * 2;
    }
    const uint32_t boff = ((wn*16 + (quad & 1)*8 + l7) * ASTR + (quad >> 1) * 8) * 2;

    float sig[2][2][4];
    const int rbase = wm*32 + (lid >> 2);
    const int cbase_w = wn*16 + (lid & 3)*2;

    for (int ci = 0; ci < 10; ++ci) {
        __syncthreads();   // A visible (ci=0); prior staging reads done
        const uint32_t wb = sbase + OFF_WB + (ci & 1) * WBSZ;
        if (ci < 9) {
            const uint32_t wbn = sbase + OFF_WB + ((ci + 1) & 1) * WBSZ;
            #pragma unroll
            for (int p = 0; p < 4; ++p) {
                int idx = p * 256 + t;
                int n = idx >> 4, seg = idx & 15;
                cp16(wbn + n * 272 + seg * 16,
                     g_wH + (size_t)(noff[ci+1] + n) * 128 + seg * 8);
            }
            cp_commit();
            cp_wait1();
        } else {
            cp_wait0();
        }
        __syncthreads();

        float acc[2][2][4];
        #pragma unroll
        for (int mf = 0; mf < 2; ++mf)
            #pragma unroll
            for (int nf = 0; nf < 2; ++nf)
                #pragma unroll
                for (int q = 0; q < 4; ++q) acc[mf][nf][q] = 0.f;

        #pragma unroll
        for (int ks = 0; ks < 128; ks += 16) {
            uint32_t ah[2][4], bh[2][2], r4[4];
            ldmx4(ah[0], sbase + OFF_AH + aoff[0] + ks*2);
            ldmx4(ah[1], sbase + OFF_AH + aoff[1] + ks*2);
            ldmx4(r4, wb + boff + ks*2);
            bh[0][0] = r4[0]; bh[0][1] = r4[2];
            bh[1][0] = r4[1]; bh[1][1] = r4[3];
            #pragma unroll
            for (int mf = 0; mf < 2; ++mf)
                #pragma unroll
                for (int nf = 0; nf < 2; ++nf)
                    mma16816(acc[mf][nf], ah[mf], bh[nf]);
        }

        if (ci >= 8) {
            const int cb2 = (ci - 8) * 64;
            #pragma unroll
            for (int mf = 0; mf < 2; ++mf) {
                int rr0 = rbase + mf*16, rr1 = rr0 + 8;
                #pragma unroll
                for (int nf = 0; nf < 2; ++nf) {
                    int cc = cbase_w + nf*8;
                    float bg0 = __ldg(b_g + cb2 + cc);
                    float bg1 = __ldg(b_g + cb2 + cc + 1);
                    __half2 h0, h1;
                    h0.x = __float2half(1.f/(1.f + __expf(-(acc[mf][nf][0] + bg0))));
                    h0.y = __float2half(1.f/(1.f + __expf(-(acc[mf][nf][1] + bg1))));
                    h1.x = __float2half(1.f/(1.f + __expf(-(acc[mf][nf][2] + bg0))));
                    h1.y = __float2half(1.f/(1.f + __expf(-(acc[mf][nf][3] + bg1))));
                    *(__half2*)(g_gate + (size_t)(r0 + rr0) * CZ + cb2 + cc) = h0;
                    *(__half2*)(g_gate + (size_t)(r0 + rr1) * CZ + cb2 + cc) = h1;
                }
            }
        } else if ((ci & 1) == 0) {
            const float* bg = b_ab_g + noff[ci];
            #pragma unroll
            for (int mf = 0; mf < 2; ++mf)
                #pragma unroll
                for (int nf = 0; nf < 2; ++nf) {
                    int cc = cbase_w + nf*8;
                    float b0 = __ldg(bg + cc), b1 = __ldg(bg + cc + 1);
                    sig[mf][nf][0] = 1.f/(1.f + __expf(-(acc[mf][nf][0] + b0)));
                    sig[mf][nf][1] = 1.f/(1.f + __expf(-(acc[mf][nf][1] + b1)));
                    sig[mf][nf][2] = 1.f/(1.f + __expf(-(acc[mf][nf][2] + b0)));
                    sig[mf][nf][3] = 1.f/(1.f + __expf(-(acc[mf][nf][3] + b1)));
                }
        } else {
            // P chunk: hi value staged (u32 low half) into THIS chunk's dead W buffer
            const int p2 = (ci - 1) >> 1;
            const float* bp = b_ab_p + (noff[ci] - 256);
            __syncthreads();   // all warps done reading wb via ldmatrix
            uint32_t* stg = (uint32_t*)(smem + OFF_WB + (ci & 1) * WBSZ);
            #pragma unroll
            for (int mf = 0; mf < 2; ++mf) {
                int rr0 = rbase + mf*16, rr1 = rr0 + 8;
                float m0 = __ldg(mask + r0 + rr0);
                float m1 = __ldg(mask + r0 + rr1);
                #pragma unroll
                for (int nf = 0; nf < 2; ++nf) {
                    int cc = cbase_w + nf*8;
                    float b0 = __ldg(bp + cc), b1 = __ldg(bp + cc + 1);
                    stg[cc*68 + rr0]     = (uint32_t)__half_as_ushort(
                        __float2half(m0 * sig[mf][nf][0] * (acc[mf][nf][0] + b0)));
                    stg[(cc+1)*68 + rr0] = (uint32_t)__half_as_ushort(
                        __float2half(m0 * sig[mf][nf][1] * (acc[mf][nf][1] + b1)));
                    stg[cc*68 + rr1]     = (uint32_t)__half_as_ushort(
                        __float2half(m1 * sig[mf][nf][2] * (acc[mf][nf][2] + b0)));
                    stg[(cc+1)*68 + rr1] = (uint32_t)__half_as_ushort(
                        __float2half(m1 * sig[mf][nf][3] * (acc[mf][nf][3] + b1)));
                }
            }
            __syncthreads();
            __half* dH = (p2 < 2) ? g_ah : g_bh;
            const int cch = (p2 & 1) * 64 + (t >> 2);
            const int rrb = (t & 3) * 16;
            size_t off = (size_t)cch * NR + r0 + rrb;
            const uint32_t* sp = stg + (t >> 2) * 68 + rrb;
            __align__(16) unsigned short hb[16];
            #pragma unroll
            for (int i = 0; i < 16; ++i) hb[i] = (unsigned short)(sp[i] & 0xffffu);
            *(uint4*)(dH + off)     = *(uint4*)(hb);
            *(uint4*)(dH + off + 8) = *(uint4*)(hb + 8);
        }
    }
}

// =====================================================================
// Kernel 2 (v3): einsum fp16 SINGLE-pass (aH * bH).
// CTA 128x128, 512 thr, K-chunk 32, double buffer (2 tiles each).
// =====================================================================
#define KC     32
#define STR    40
#define TILE_E (128*STR)
#define BUF_E  (2*TILE_E)
#define K2_SMEM (2 * BUF_E * 2)         // 40960

__global__ void __launch_bounds__(512) k2_einsum_mma() {
    extern __shared__ __half sb[];
    const uint32_t sbase = smem_u32(sb);

    const int t   = threadIdx.x;
    const int lid = t & 31;
    const int w   = t >> 5;
    const int wm  = w >> 2;
    const int wn  = w & 3;
    const int c   = blockIdx.z;
    const int m0  = blockIdx.y * 128;
    const int n0  = blockIdx.x * 128;

    const __half* pAh = g_ah + (size_t)c * NR;
    const __half* pBh = g_bh + (size_t)c * NR;

    const int grow = t >> 2;
    const int gseg = t & 3;
    const size_t gA0 = (size_t)(m0 + grow) * NN + gseg * 8;
    const size_t gB0 = (size_t)(n0 + grow) * NN + gseg * 8;
    const uint32_t sw = (grow * STR + gseg * 8) * 2;

    const int quad = lid >> 3;
    const int l7   = lid & 7;
    uint32_t aoff[2];
    #pragma unroll
    for (int mf = 0; mf < 2; ++mf) {
        int r = wm*32 + mf*16 + (quad & 1)*8 + l7;
        aoff[mf] = (r * STR + (quad >> 1) * 8) * 2;
    }
    uint32_t boff[4];
    #pragma unroll
    for (int nf = 0; nf < 4; ++nf) {
        int r = wn*32 + nf*8 + l7;
        boff[nf] = (r * STR + ((lid >> 3) & 1) * 8) * 2;
    }

    float d[2][4][4];
    #pragma unroll
    for (int mf = 0; mf < 2; ++mf)
        #pragma unroll
        for (int nf = 0; nf < 4; ++nf)
            #pragma unroll
            for (int q = 0; q < 4; ++q) d[mf][nf][q] = 0.f;

    {
        uint32_t b0 = sbase;
        cp16(b0 + 0*TILE_E*2 + sw, pAh + gA0);
        cp16(b0 + 1*TILE_E*2 + sw, pBh + gB0);
        cp_commit();
    }

    for (int ch = 0; ch < 16; ++ch) {
        if (ch < 15) {
            uint32_t bb = sbase + ((ch + 1) & 1) * BUF_E * 2;
            int kk = (ch + 1) * KC;
            cp16(bb + 0*TILE_E*2 + sw, pAh + gA0 + kk);
            cp16(bb + 1*TILE_E*2 + sw, pBh + gB0 + kk);
            cp_commit();
            cp_wait1();
        } else {
            cp_wait0();
        }
        __syncthreads();

        const uint32_t bb = sbase + (ch & 1) * BUF_E * 2;
        const uint32_t bAH = bb;
        const uint32_t bBH = bb + TILE_E*2;

        #pragma unroll
        for (int ks = 0; ks < KC; ks += 16) {
            uint32_t ah[2][4], bh[4][2];
            #pragma unroll
            for (int mf = 0; mf < 2; ++mf) ldmx4(ah[mf], bAH + aoff[mf] + ks*2);
            #pragma unroll
            for (int nf = 0; nf < 4; ++nf) ldmx2(bh[nf], bBH + boff[nf] + ks*2);
            #pragma unroll
            for (int mf = 0; mf < 2; ++mf)
                #pragma unroll
                for (int nf = 0; nf < 4; ++nf)
                    mma16816(d[mf][nf], ah[mf], bh[nf]);
        }
        __syncthreads();
    }

    float* X = g_x + (size_t)c * NR;
    const int rb = m0 + wm*32 + (lid >> 2);
    const int cb = n0 + wn*32 + (lid & 3) * 2;
    #pragma unroll
    for (int mf = 0; mf < 2; ++mf)
        #pragma unroll
        for (int nf = 0; nf < 4; ++nf) {
            int row = rb + mf*16;
            int col = cb + nf*8;
            *(float2*)(X + (size_t)row * NN + col) =
                make_float2(d[mf][nf][0], d[mf][nf][1]);
            *(float2*)(X + (size_t)(row + 8) * NN + col) =
                make_float2(d[mf][nf][2], d[mf][nf][3]);
        }
}

// =====================================================================
// Kernel 3 (v4): gather x -> LN -> @ w_z (fp16 3-pass) -> *gate(fp16) -> out.
// =====================================================================
#define K3_AH 33792
#define K3_AL 51200
#define K3_WH 68608
#define K3_WL 86016
#define K3_SMEM 103424

__global__ void __launch_bounds__(256, 2) k3_mma(
    const float* __restrict__ b_z,
    const float* __restrict__ ln_g, const float* __restrict__ ln_b,
    float* __restrict__ out)
{
    extern __shared__ char smem[];
    const uint32_t sbase = smem_u32(smem);
    float* xS = (float*)smem;                    // [row][c] stride 132
    const int t   = threadIdx.x;
    const int lid = t & 31;
    const int w   = t >> 5;
    const int wm  = w >> 2;
    const int wn  = w & 3;
    const int r0  = blockIdx.x * 64;
    const int i0  = r0 >> 9;
    const int j0  = r0 & 511;

    {
        const int joff = t & 63, part = t >> 6;
        const float* src = g_x + (size_t)(part*32) * NR + (size_t)i0 * NN + j0 + joff;
        #pragma unroll
        for (int q = 0; q < 32; ++q)
            xS[joff*132 + part*32 + q] = src[(size_t)q * NR];
    }
    __syncthreads();

    {
        const int row = t >> 2, qt = t & 3;
        const float* zr = xS + row * 132 + qt * 32;
        float s = 0.f, s2 = 0.f;
        #pragma unroll
        for (int q = 0; q < 8; ++q) {
            float4 v = *(const float4*)(zr + q * 4);
            s  += v.x + v.y + v.z + v.w;
            s2 += v.x*v.x + v.y*v.y + v.z*v.z + v.w*v.w;
        }
        s  += __shfl_xor_sync(0xffffffffu, s, 1);
        s2 += __shfl_xor_sync(0xffffffffu, s2, 1);
        s  += __shfl_xor_sync(0xffffffffu, s, 2);
        s2 += __shfl_xor_sync(0xffffffffu, s2, 2);
        float mu  = s * (1.0f/128.0f);
        float var = fmaxf(s2 * (1.0f/128.0f) - mu*mu, 0.f);
        float rs  = rsqrtf(var + EPSV);

        __half* aH = (__half*)(smem + K3_AH) + row * ASTR;
        __half* aL = (__half*)(smem + K3_AL) + row * ASTR;
        #pragma unroll
        for (int q8 = 0; q8 < 4; ++q8) {
            __align__(16) __half hb[8], lb[8];
            #pragma unroll
            for (int j = 0; j < 8; ++j) {
                int c = qt * 32 + q8 * 8 + j;
                float v = (zr[q8*8 + j] - mu) * rs * __ldg(ln_g + c) + __ldg(ln_b + c);
                __half h = __float2half(v);
                hb[j] = h;
                lb[j] = __float2half(v - __half2float(h));
            }
            *(uint4*)(aH + qt*32 + q8*8) = *(uint4*)hb;
            *(uint4*)(aL + qt*32 + q8*8) = *(uint4*)lb;
        }
    }

    const int quad = lid >> 3;
    const int l7   = lid & 7;
    uint32_t aoff[2];
    #pragma unroll
    for (int mf = 0; mf < 2; ++mf) {
        int r = wm*32 + mf*16 + (quad & 1)*8 + l7;
        aoff[mf] = (r * ASTR + (quad >> 1) * 8) * 2;
    }
    const uint32_t boff = ((wn*16 + (quad & 1)*8 + l7) * ASTR + (quad >> 1) * 8) * 2;
    const int rbase = wm*32 + (lid >> 2);
    const int cbase_w = wn*16 + (lid & 3)*2;

    for (int ci = 0; ci < 2; ++ci) {
        __syncthreads();
        #pragma unroll
        for (int p = 0; p < 4; ++p) {
            int idx = p * 256 + t;
            int n = idx >> 4, seg = idx & 15;
            cp16(sbase + K3_WH + n * 272 + seg * 16,
                 g_wH + (size_t)(640 + ci*64 + n) * 128 + seg * 8);
            cp16(sbase + K3_WL + n * 272 + seg * 16,
                 g_wL + (size_t)(640 + ci*64 + n) * 128 + seg * 8);
        }
        cp_commit(); cp_wait0();
        __syncthreads();

        float acc[2][2][4];
        #pragma unroll
        for (int mf = 0; mf < 2; ++mf)
            #pragma unroll
            for (int nf = 0; nf < 2; ++nf)
                #pragma unroll
                for (int q = 0; q < 4; ++q) acc[mf][nf][q] = 0.f;

        #pragma unroll
        for (int ks = 0; ks < 128; ks += 16) {
            uint32_t ah[2][4], al[2][4], bh[2][2], bl[2][2], r4[4];
            ldmx4(ah[0], sbase + K3_AH + aoff[0] + ks*2);
            ldmx4(ah[1], sbase + K3_AH + aoff[1] + ks*2);
            ldmx4(al[0], sbase + K3_AL + aoff[0] + ks*2);
            ldmx4(al[1], sbase + K3_AL + aoff[1] + ks*2);
            ldmx4(r4, sbase + K3_WH + boff + ks*2);
            bh[0][0] = r4[0]; bh[0][1] = r4[2];
            bh[1][0] = r4[1]; bh[1][1] = r4[3];
            ldmx4(r4, sbase + K3_WL + boff + ks*2);
            bl[0][0] = r4[0]; bl[0][1] = r4[2];
            bl[1][0] = r4[1]; bl[1][1] = r4[3];
            #pragma unroll
            for (int mf = 0; mf < 2; ++mf)
                #pragma unroll
                for (int nf = 0; nf < 2; ++nf)
                    mma16816(acc[mf][nf], ah[mf], bh[nf]);
            #pragma unroll
            for (int mf = 0; mf < 2; ++mf)
                #pragma unroll
                for (int nf = 0; nf < 2; ++nf)
                    mma16816(acc[mf][nf], ah[mf], bl[nf]);
            #pragma unroll
            for (int mf = 0; mf < 2; ++mf)
                #pragma unroll
                for (int nf = 0; nf < 2; ++nf)
                    mma16816(acc[mf][nf], al[mf], bh[nf]);
        }

        const int cb2 = ci * 64;
        #pragma unroll
        for (int mf = 0; mf < 2; ++mf) {
            int rr0 = rbase + mf*16, rr1 = rr0 + 8;
            #pragma unroll
            for (int nf = 0; nf < 2; ++nf) {
                int cc = cbase_w + nf*8;
                float b0 = __ldg(b_z + cb2 + cc);
                float b1 = __ldg(b_z + cb2 + cc + 1);
                float2 gg0 = __half22float2(*(const __half2*)(g_gate + (size_t)(r0 + rr0) * CZ + cb2 + cc));
                float2 gg1 = __half22float2(*(const __half2*)(g_gate + (size_t)(r0 + rr1) * CZ + cb2 + cc));
                float2 v0, v1;
                v0.x = (acc[mf][nf][0] + b0) * gg0.x;
                v0.y = (acc[mf][nf][1] + b1) * gg0.y;
                v1.x = (acc[mf][nf][2] + b0) * gg1.x;
                v1.y = (acc[mf][nf][3] + b1) * gg1.y;
                *(float2*)(out + (size_t)(r0 + rr0) * CZ + cb2 + cc) = v0;
                *(float2*)(out + (size_t)(r0 + rr1) * CZ + cb2 + cc) = v1;
            }
        }
    }
}

// =====================================================================
extern "C" void kernel_launch(void* const* d_in, const int* in_sizes, int n_in,
                              void* d_out, int out_size) {
    const float* z       = (const float*)d_in[0];
    const float* mask    = (const float*)d_in[1];
    const float* w_ab_p  = (const float*)d_in[2];
    const float* b_ab_p  = (const float*)d_in[3];
    const float* w_ab_g  = (const float*)d_in[4];
    const float* b_ab_g  = (const float*)d_in[5];
    const float* w_g     = (const float*)d_in[6];
    const float* b_g     = (const float*)d_in[7];
    const float* w_z     = (const float*)d_in[8];
    const float* b_z     = (const float*)d_in[9];
    const float* ln_in_g = (const float*)d_in[10];
    const float* ln_in_b = (const float*)d_in[11];
    const float* ln_out_g= (const float*)d_in[12];
    const float* ln_out_b= (const float*)d_in[13];
    float* out = (float*)d_out;

    cudaFuncSetAttribute(k1_mma,        cudaFuncAttributeMaxDynamicSharedMemorySize, K1_SMEM);
    cudaFuncSetAttribute(k2_einsum_mma, cudaFuncAttributeMaxDynamicSharedMemorySize, K2_SMEM);
    cudaFuncSetAttribute(k3_mma,        cudaFuncAttributeMaxDynamicSharedMemorySize, K3_SMEM);

    k0_wsplit<<<384, 256>>>(w_ab_g, w_ab_p, w_g, w_z);
    k1_mma<<<NR / 64, 256, K1_SMEM>>>(z, mask, b_ab_p, b_ab_g, b_g,
                                      ln_in_g, ln_in_b);
    k2_einsum_mma<<<dim3(4, 4, 128), 512, K2_SMEM>>>();
    k3_mma<<<NR / 64, 256, K3_SMEM>>>(b_z, ln_out_g, ln_out_b, out);
}

// round 13
// speedup vs baseline: 1.0096x; 1.0096x over previous
#include <cuda_runtime.h>
#include <cuda_fp16.h>
#include <math.h>
#include <cstdint>

#define NN   512
#define CZ   128
#define NR   (NN*NN)          // 262144
#define EPSV 1e-5f

// ---------------- scratch (device globals; alloc-free) ----------------
__device__ __half g_ah[(size_t)CZ * NR];   // a hi [c][i][k]
__device__ __half g_bh[(size_t)CZ * NR];   // b hi [c][j][k]
__device__ __half g_gate[(size_t)NR * CZ]; // gate[r][c]  (fp16)
__device__ __half g_x[(size_t)CZ * NR];    // x[c][i][j]  (fp16, L2-resident)
__device__ __half g_wH[768 * 128];         // packed weights hi [n][k]
__device__ __half g_wL[768 * 128];         // packed weights lo [n][k]

static __device__ __forceinline__ uint32_t smem_u32(const void* p) {
    return (uint32_t)__cvta_generic_to_shared(p);
}
static __device__ __forceinline__ void cp16(uint32_t dst, const void* src) {
    asm volatile("cp.async.cg.shared.global [%0], [%1], 16;" :: "r"(dst), "l"(src));
}
static __device__ __forceinline__ void cp_commit() {
    asm volatile("cp.async.commit_group;" ::: "memory");
}
static __device__ __forceinline__ void cp_wait1() {
    asm volatile("cp.async.wait_group 1;" ::: "memory");
}
static __device__ __forceinline__ void cp_wait0() {
    asm volatile("cp.async.wait_group 0;" ::: "memory");
}
static __device__ __forceinline__ void ldmx4(uint32_t* r, uint32_t addr) {
    asm volatile("ldmatrix.sync.aligned.m8n8.x4.shared.b16 {%0,%1,%2,%3}, [%4];"
                 : "=r"(r[0]), "=r"(r[1]), "=r"(r[2]), "=r"(r[3]) : "r"(addr));
}
static __device__ __forceinline__ void ldmx2(uint32_t* r, uint32_t addr) {
    asm volatile("ldmatrix.sync.aligned.m8n8.x2.shared.b16 {%0,%1}, [%2];"
                 : "=r"(r[0]), "=r"(r[1]) : "r"(addr));
}
static __device__ __forceinline__ void mma16816(float* d, const uint32_t* a, const uint32_t* b) {
    asm volatile("mma.sync.aligned.m16n8k16.row.col.f32.f16.f16.f32 "
                 "{%0,%1,%2,%3}, {%4,%5,%6,%7}, {%8,%9}, {%0,%1,%2,%3};"
                 : "+f"(d[0]), "+f"(d[1]), "+f"(d[2]), "+f"(d[3])
                 : "r"(a[0]), "r"(a[1]), "r"(a[2]), "r"(a[3]), "r"(b[0]), "r"(b[1]));
}

// =====================================================================
// Kernel 0: split weights into fp16 hi/lo, transposed to [n][k].
// n: 0-255 = w_ab_g, 256-511 = w_ab_p, 512-639 = w_g, 640-767 = w_z
// =====================================================================
__global__ void __launch_bounds__(256) k0_wsplit(
    const float* __restrict__ w_ab_g, const float* __restrict__ w_ab_p,
    const float* __restrict__ w_g,   const float* __restrict__ w_z)
{
    int idx = blockIdx.x * 256 + threadIdx.x;   // 384 blocks
    if (idx >= 768 * 128) return;
    int n = idx >> 7, k = idx & 127;
    float v;
    if (n < 256)      v = w_ab_g[k * 256 + n];
    else if (n < 512) v = w_ab_p[k * 256 + (n - 256)];
    else if (n < 640) v = w_g[k * 128 + (n - 512)];
    else              v = w_z[k * 128 + (n - 640)];
    __half h = __float2half(v);
    g_wH[idx] = h;
    g_wL[idx] = __float2half(v - __half2float(h));
}

// =====================================================================
// Kernel 1 (v5): LN(z) + projections, fp16 SINGLE-pass (znH * WH).
// 4096 CTAs x 64 rows, 256 thr (8 warps: 2m x 4n), warp tile 32x16.
// =====================================================================
#define ASTR   136
#define OFF_AH 0                       // 17408 B
#define OFF_WB 17408                   // two 17408-B WH buffers
#define WBSZ   17408
#define K1_SMEM 52224

__global__ void __launch_bounds__(256, 2) k1_mma(
    const float* __restrict__ z, const float* __restrict__ mask,
    const float* __restrict__ b_ab_p, const float* __restrict__ b_ab_g,
    const float* __restrict__ b_g,
    const float* __restrict__ ln_g,  const float* __restrict__ ln_b)
{
    extern __shared__ char smem[];
    const uint32_t sbase = smem_u32(smem);
    const int t   = threadIdx.x;
    const int lid = t & 31;
    const int w   = t >> 5;
    const int wm  = w >> 2;
    const int wn  = w & 3;
    const int r0  = blockIdx.x * 64;

    const int noff[10] = {0, 256, 64, 320, 128, 384, 192, 448, 512, 576};

    // ---- prefetch WH chunk 0 into buffer 0 ----
    {
        #pragma unroll
        for (int p = 0; p < 4; ++p) {
            int idx = p * 256 + t;
            int n = idx >> 4, seg = idx & 15;
            cp16(sbase + OFF_WB + n * 272 + seg * 16,
                 g_wH + (size_t)n * 128 + seg * 8);
        }
        cp_commit();
    }

    // ---- z via LDG -> LN (4 thr/row, shfl) -> fp16 hi smem ----
    {
        const int row = t >> 2, qt = t & 3;
        const float4* zr = (const float4*)(z + (size_t)(r0 + row) * CZ + qt * 32);
        float4 v[8];
        #pragma unroll
        for (int q = 0; q < 8; ++q) v[q] = __ldg(zr + q);
        float s = 0.f, s2 = 0.f;
        #pragma unroll
        for (int q = 0; q < 8; ++q) {
            s  += v[q].x + v[q].y + v[q].z + v[q].w;
            s2 += v[q].x*v[q].x + v[q].y*v[q].y + v[q].z*v[q].z + v[q].w*v[q].w;
        }
        s  += __shfl_xor_sync(0xffffffffu, s, 1);
        s2 += __shfl_xor_sync(0xffffffffu, s2, 1);
        s  += __shfl_xor_sync(0xffffffffu, s, 2);
        s2 += __shfl_xor_sync(0xffffffffu, s2, 2);
        float mu  = s * (1.0f/128.0f);
        float var = fmaxf(s2 * (1.0f/128.0f) - mu*mu, 0.f);
        float rs  = rsqrtf(var + EPSV);

        __half* aH = (__half*)(smem + OFF_AH) + row * ASTR + qt * 32;
        #pragma unroll
        for (int q8 = 0; q8 < 4; ++q8) {
            const float vv[8] = {v[q8*2].x, v[q8*2].y, v[q8*2].z, v[q8*2].w,
                                 v[q8*2+1].x, v[q8*2+1].y, v[q8*2+1].z, v[q8*2+1].w};
            __align__(16) __half hb[8];
            #pragma unroll
            for (int j = 0; j < 8; ++j) {
                int c = qt * 32 + q8 * 8 + j;
                hb[j] = __float2half((vv[j] - mu) * rs * __ldg(ln_g + c) + __ldg(ln_b + c));
            }
            *(uint4*)(aH + q8*8) = *(uint4*)hb;
        }
    }

    const int quad = lid >> 3;
    const int l7   = lid & 7;
    uint32_t aoff[2];
    #pragma unroll
    for (int mf = 0; mf < 2; ++mf) {
        int r = wm*32 + mf*16 + (quad & 1)*8 + l7;
        aoff[mf] = (r * ASTR + (quad >> 1) * 8) * 2;
    }
    const uint32_t boff = ((wn*16 + (quad & 1)*8 + l7) * ASTR + (quad >> 1) * 8) * 2;

    float sig[2][2][4];
    const int rbase = wm*32 + (lid >> 2);
    const int cbase_w = wn*16 + (lid & 3)*2;

    for (int ci = 0; ci < 10; ++ci) {
        __syncthreads();
        const uint32_t wb = sbase + OFF_WB + (ci & 1) * WBSZ;
        if (ci < 9) {
            const uint32_t wbn = sbase + OFF_WB + ((ci + 1) & 1) * WBSZ;
            #pragma unroll
            for (int p = 0; p < 4; ++p) {
                int idx = p * 256 + t;
                int n = idx >> 4, seg = idx & 15;
                cp16(wbn + n * 272 + seg * 16,
                     g_wH + (size_t)(noff[ci+1] + n) * 128 + seg * 8);
            }
            cp_commit();
            cp_wait1();
        } else {
            cp_wait0();
        }
        __syncthreads();

        float acc[2][2][4];
        #pragma unroll
        for (int mf = 0; mf < 2; ++mf)
            #pragma unroll
            for (int nf = 0; nf < 2; ++nf)
                #pragma unroll
                for (int q = 0; q < 4; ++q) acc[mf][nf][q] = 0.f;

        #pragma unroll
        for (int ks = 0; ks < 128; ks += 16) {
            uint32_t ah[2][4], bh[2][2], r4[4];
            ldmx4(ah[0], sbase + OFF_AH + aoff[0] + ks*2);
            ldmx4(ah[1], sbase + OFF_AH + aoff[1] + ks*2);
            ldmx4(r4, wb + boff + ks*2);
            bh[0][0] = r4[0]; bh[0][1] = r4[2];
            bh[1][0] = r4[1]; bh[1][1] = r4[3];
            #pragma unroll
            for (int mf = 0; mf < 2; ++mf)
                #pragma unroll
                for (int nf = 0; nf < 2; ++nf)
                    mma16816(acc[mf][nf], ah[mf], bh[nf]);
        }

        if (ci >= 8) {
            const int cb2 = (ci - 8) * 64;
            #pragma unroll
            for (int mf = 0; mf < 2; ++mf) {
                int rr0 = rbase + mf*16, rr1 = rr0 + 8;
                #pragma unroll
                for (int nf = 0; nf < 2; ++nf) {
                    int cc = cbase_w + nf*8;
                    float bg0 = __ldg(b_g + cb2 + cc);
                    float bg1 = __ldg(b_g + cb2 + cc + 1);
                    __half2 h0, h1;
                    h0.x = __float2half(1.f/(1.f + __expf(-(acc[mf][nf][0] + bg0))));
                    h0.y = __float2half(1.f/(1.f + __expf(-(acc[mf][nf][1] + bg1))));
                    h1.x = __float2half(1.f/(1.f + __expf(-(acc[mf][nf][2] + bg0))));
                    h1.y = __float2half(1.f/(1.f + __expf(-(acc[mf][nf][3] + bg1))));
                    *(__half2*)(g_gate + (size_t)(r0 + rr0) * CZ + cb2 + cc) = h0;
                    *(__half2*)(g_gate + (size_t)(r0 + rr1) * CZ + cb2 + cc) = h1;
                }
            }
        } else if ((ci & 1) == 0) {
            const float* bg = b_ab_g + noff[ci];
            #pragma unroll
            for (int mf = 0; mf < 2; ++mf)
                #pragma unroll
                for (int nf = 0; nf < 2; ++nf) {
                    int cc = cbase_w + nf*8;
                    float b0 = __ldg(bg + cc), b1 = __ldg(bg + cc + 1);
                    sig[mf][nf][0] = 1.f/(1.f + __expf(-(acc[mf][nf][0] + b0)));
                    sig[mf][nf][1] = 1.f/(1.f + __expf(-(acc[mf][nf][1] + b1)));
                    sig[mf][nf][2] = 1.f/(1.f + __expf(-(acc[mf][nf][2] + b0)));
                    sig[mf][nf][3] = 1.f/(1.f + __expf(-(acc[mf][nf][3] + b1)));
                }
        } else {
            const int p2 = (ci - 1) >> 1;
            const float* bp = b_ab_p + (noff[ci] - 256);
            __syncthreads();
            uint32_t* stg = (uint32_t*)(smem + OFF_WB + (ci & 1) * WBSZ);
            #pragma unroll
            for (int mf = 0; mf < 2; ++mf) {
                int rr0 = rbase + mf*16, rr1 = rr0 + 8;
                float m0 = __ldg(mask + r0 + rr0);
                float m1 = __ldg(mask + r0 + rr1);
                #pragma unroll
                for (int nf = 0; nf < 2; ++nf) {
                    int cc = cbase_w + nf*8;
                    float b0 = __ldg(bp + cc), b1 = __ldg(bp + cc + 1);
                    stg[cc*68 + rr0]     = (uint32_t)__half_as_ushort(
                        __float2half(m0 * sig[mf][nf][0] * (acc[mf][nf][0] + b0)));
                    stg[(cc+1)*68 + rr0] = (uint32_t)__half_as_ushort(
                        __float2half(m0 * sig[mf][nf][1] * (acc[mf][nf][1] + b1)));
                    stg[cc*68 + rr1]     = (uint32_t)__half_as_ushort(
                        __float2half(m1 * sig[mf][nf][2] * (acc[mf][nf][2] + b0)));
                    stg[(cc+1)*68 + rr1] = (uint32_t)__half_as_ushort(
                        __float2half(m1 * sig[mf][nf][3] * (acc[mf][nf][3] + b1)));
                }
            }
            __syncthreads();
            __half* dH = (p2 < 2) ? g_ah : g_bh;
            const int cch = (p2 & 1) * 64 + (t >> 2);
            const int rrb = (t & 3) * 16;
            size_t off = (size_t)cch * NR + r0 + rrb;
            const uint32_t* sp = stg + (t >> 2) * 68 + rrb;
            __align__(16) unsigned short hb[16];
            #pragma unroll
            for (int i = 0; i < 16; ++i) hb[i] = (unsigned short)(sp[i] & 0xffffu);
            *(uint4*)(dH + off)     = *(uint4*)(hb);
            *(uint4*)(dH + off + 8) = *(uint4*)(hb + 8);
        }
    }
}

// =====================================================================
// Kernel 2 (v4): einsum fp16 single-pass; X written fp16 (L2-resident).
// =====================================================================
#define KC     32
#define STR    40
#define TILE_E (128*STR)
#define BUF_E  (2*TILE_E)
#define K2_SMEM (2 * BUF_E * 2)         // 40960

__global__ void __launch_bounds__(512) k2_einsum_mma() {
    extern __shared__ __half sb[];
    const uint32_t sbase = smem_u32(sb);

    const int t   = threadIdx.x;
    const int lid = t & 31;
    const int w   = t >> 5;
    const int wm  = w >> 2;
    const int wn  = w & 3;
    const int c   = blockIdx.z;
    const int m0  = blockIdx.y * 128;
    const int n0  = blockIdx.x * 128;

    const __half* pAh = g_ah + (size_t)c * NR;
    const __half* pBh = g_bh + (size_t)c * NR;

    const int grow = t >> 2;
    const int gseg = t & 3;
    const size_t gA0 = (size_t)(m0 + grow) * NN + gseg * 8;
    const size_t gB0 = (size_t)(n0 + grow) * NN + gseg * 8;
    const uint32_t sw = (grow * STR + gseg * 8) * 2;

    const int quad = lid >> 3;
    const int l7   = lid & 7;
    uint32_t aoff[2];
    #pragma unroll
    for (int mf = 0; mf < 2; ++mf) {
        int r = wm*32 + mf*16 + (quad & 1)*8 + l7;
        aoff[mf] = (r * STR + (quad >> 1) * 8) * 2;
    }
    uint32_t boff[4];
    #pragma unroll
    for (int nf = 0; nf < 4; ++nf) {
        int r = wn*32 + nf*8 + l7;
        boff[nf] = (r * STR + ((lid >> 3) & 1) * 8) * 2;
    }

    float d[2][4][4];
    #pragma unroll
    for (int mf = 0; mf < 2; ++mf)
        #pragma unroll
        for (int nf = 0; nf < 4; ++nf)
            #pragma unroll
            for (int q = 0; q < 4; ++q) d[mf][nf][q] = 0.f;

    {
        uint32_t b0 = sbase;
        cp16(b0 + 0*TILE_E*2 + sw, pAh + gA0);
        cp16(b0 + 1*TILE_E*2 + sw, pBh + gB0);
        cp_commit();
    }

    for (int ch = 0; ch < 16; ++ch) {
        if (ch < 15) {
            uint32_t bb = sbase + ((ch + 1) & 1) * BUF_E * 2;
            int kk = (ch + 1) * KC;
            cp16(bb + 0*TILE_E*2 + sw, pAh + gA0 + kk);
            cp16(bb + 1*TILE_E*2 + sw, pBh + gB0 + kk);
            cp_commit();
            cp_wait1();
        } else {
            cp_wait0();
        }
        __syncthreads();

        const uint32_t bb = sbase + (ch & 1) * BUF_E * 2;
        const uint32_t bAH = bb;
        const uint32_t bBH = bb + TILE_E*2;

        #pragma unroll
        for (int ks = 0; ks < KC; ks += 16) {
            uint32_t ah[2][4], bh[4][2];
            #pragma unroll
            for (int mf = 0; mf < 2; ++mf) ldmx4(ah[mf], bAH + aoff[mf] + ks*2);
            #pragma unroll
            for (int nf = 0; nf < 4; ++nf) ldmx2(bh[nf], bBH + boff[nf] + ks*2);
            #pragma unroll
            for (int mf = 0; mf < 2; ++mf)
                #pragma unroll
                for (int nf = 0; nf < 4; ++nf)
                    mma16816(d[mf][nf], ah[mf], bh[nf]);
        }
        __syncthreads();
    }

    __half* X = g_x + (size_t)c * NR;
    const int rb = m0 + wm*32 + (lid >> 2);
    const int cb = n0 + wn*32 + (lid & 3) * 2;
    #pragma unroll
    for (int mf = 0; mf < 2; ++mf)
        #pragma unroll
        for (int nf = 0; nf < 4; ++nf) {
            int row = rb + mf*16;
            int col = cb + nf*8;
            *(__half2*)(X + (size_t)row * NN + col) =
                __floats2half2_rn(d[mf][nf][0], d[mf][nf][1]);
            *(__half2*)(X + (size_t)(row + 8) * NN + col) =
                __floats2half2_rn(d[mf][nf][2], d[mf][nf][3]);
        }
}

// =====================================================================
// Kernel 3 (v5): gather x (fp16, L2) -> LN -> @ w_z (fp16 3-pass) -> *gate -> out.
// =====================================================================
#define K3_AH 33792
#define K3_AL 51200
#define K3_WH 68608
#define K3_WL 86016
#define K3_SMEM 103424

__global__ void __launch_bounds__(256, 2) k3_mma(
    const float* __restrict__ b_z,
    const float* __restrict__ ln_g, const float* __restrict__ ln_b,
    float* __restrict__ out)
{
    extern __shared__ char smem[];
    const uint32_t sbase = smem_u32(smem);
    float* xS = (float*)smem;                    // [row][c] stride 132
    const int t   = threadIdx.x;
    const int lid = t & 31;
    const int w   = t >> 5;
    const int wm  = w >> 2;
    const int wn  = w & 3;
    const int r0  = blockIdx.x * 64;
    const int i0  = r0 >> 9;
    const int j0  = r0 & 511;

    {
        const int joff = t & 63, part = t >> 6;
        const __half* src = g_x + (size_t)(part*32) * NR + (size_t)i0 * NN + j0 + joff;
        #pragma unroll
        for (int q = 0; q < 32; ++q)
            xS[joff*132 + part*32 + q] = __half2float(src[(size_t)q * NR]);
    }
    __syncthreads();

    {
        const int row = t >> 2, qt = t & 3;
        const float* zr = xS + row * 132 + qt * 32;
        float s = 0.f, s2 = 0.f;
        #pragma unroll
        for (int q = 0; q < 8; ++q) {
            float4 v = *(const float4*)(zr + q * 4);
            s  += v.x + v.y + v.z + v.w;
            s2 += v.x*v.x + v.y*v.y + v.z*v.z + v.w*v.w;
        }
        s  += __shfl_xor_sync(0xffffffffu, s, 1);
        s2 += __shfl_xor_sync(0xffffffffu, s2, 1);
        s  += __shfl_xor_sync(0xffffffffu, s, 2);
        s2 += __shfl_xor_sync(0xffffffffu, s2, 2);
        float mu  = s * (1.0f/128.0f);
        float var = fmaxf(s2 * (1.0f/128.0f) - mu*mu, 0.f);
        float rs  = rsqrtf(var + EPSV);

        __half* aH = (__half*)(smem + K3_AH) + row * ASTR;
        __half* aL = (__half*)(smem + K3_AL) + row * ASTR;
        #pragma unroll
        for (int q8 = 0; q8 < 4; ++q8) {
            __align__(16) __half hb[8], lb[8];
            #pragma unroll
            for (int j = 0; j < 8; ++j) {
                int c = qt * 32 + q8 * 8 + j;
                float v = (zr[q8*8 + j] - mu) * rs * __ldg(ln_g + c) + __ldg(ln_b + c);
                __half h = __float2half(v);
                hb[j] = h;
                lb[j] = __float2half(v - __half2float(h));
            }
            *(uint4*)(aH + qt*32 + q8*8) = *(uint4*)hb;
            *(uint4*)(aL + qt*32 + q8*8) = *(uint4*)lb;
        }
    }

    const int quad = lid >> 3;
    const int l7   = lid & 7;
    uint32_t aoff[2];
    #pragma unroll
    for (int mf = 0; mf < 2; ++mf) {
        int r = wm*32 + mf*16 + (quad & 1)*8 + l7;
        aoff[mf] = (r * ASTR + (quad >> 1) * 8) * 2;
    }
    const uint32_t boff = ((wn*16 + (quad & 1)*8 + l7) * ASTR + (quad >> 1) * 8) * 2;
    const int rbase = wm*32 + (lid >> 2);
    const int cbase_w = wn*16 + (lid & 3)*2;

    for (int ci = 0; ci < 2; ++ci) {
        __syncthreads();
        #pragma unroll
        for (int p = 0; p < 4; ++p) {
            int idx = p * 256 + t;
            int n = idx >> 4, seg = idx & 15;
            cp16(sbase + K3_WH + n * 272 + seg * 16,
                 g_wH + (size_t)(640 + ci*64 + n) * 128 + seg * 8);
            cp16(sbase + K3_WL + n * 272 + seg * 16,
                 g_wL + (size_t)(640 + ci*64 + n) * 128 + seg * 8);
        }
        cp_commit(); cp_wait0();
        __syncthreads();

        float acc[2][2][4];
        #pragma unroll
        for (int mf = 0; mf < 2; ++mf)
            #pragma unroll
            for (int nf = 0; nf < 2; ++nf)
                #pragma unroll
                for (int q = 0; q < 4; ++q) acc[mf][nf][q] = 0.f;

        #pragma unroll
        for (int ks = 0; ks < 128; ks += 16) {
            uint32_t ah[2][4], al[2][4], bh[2][2], bl[2][2], r4[4];
            ldmx4(ah[0], sbase + K3_AH + aoff[0] + ks*2);
            ldmx4(ah[1], sbase + K3_AH + aoff[1] + ks*2);
            ldmx4(al[0], sbase + K3_AL + aoff[0] + ks*2);
            ldmx4(al[1], sbase + K3_AL + aoff[1] + ks*2);
            ldmx4(r4, sbase + K3_WH + boff + ks*2);
            bh[0][0] = r4[0]; bh[0][1] = r4[2];
            bh[1][0] = r4[1]; bh[1][1] = r4[3];
            ldmx4(r4, sbase + K3_WL + boff + ks*2);
            bl[0][0] = r4[0]; bl[0][1] = r4[2];
            bl[1][0] = r4[1]; bl[1][1] = r4[3];
            #pragma unroll
            for (int mf = 0; mf < 2; ++mf)
                #pragma unroll
                for (int nf = 0; nf < 2; ++nf)
                    mma16816(acc[mf][nf], ah[mf], bh[nf]);
            #pragma unroll
            for (int mf = 0; mf < 2; ++mf)
                #pragma unroll
                for (int nf = 0; nf < 2; ++nf)
                    mma16816(acc[mf][nf], ah[mf], bl[nf]);
            #pragma unroll
            for (int mf = 0; mf < 2; ++mf)
                #pragma unroll
                for (int nf = 0; nf < 2; ++nf)
                    mma16816(acc[mf][nf], al[mf], bh[nf]);
        }

        const int cb2 = ci * 64;
        #pragma unroll
        for (int mf = 0; mf < 2; ++mf) {
            int rr0 = rbase + mf*16, rr1 = rr0 + 8;
            #pragma unroll
            for (int nf = 0; nf < 2; ++nf) {
                int cc = cbase_w + nf*8;
                float b0 = __ldg(b_z + cb2 + cc);
                float b1 = __ldg(b_z + cb2 + cc + 1);
                float2 gg0 = __half22float2(*(const __half2*)(g_gate + (size_t)(r0 + rr0) * CZ + cb2 + cc));
                float2 gg1 = __half22float2(*(const __half2*)(g_gate + (size_t)(r0 + rr1) * CZ + cb2 + cc));
                float2 v0, v1;
                v0.x = (acc[mf][nf][0] + b0) * gg0.x;
                v0.y = (acc[mf][nf][1] + b1) * gg0.y;
                v1.x = (acc[mf][nf][2] + b0) * gg1.x;
                v1.y = (acc[mf][nf][3] + b1) * gg1.y;
                *(float2*)(out + (size_t)(r0 + rr0) * CZ + cb2 + cc) = v0;
                *(float2*)(out + (size_t)(r0 + rr1) * CZ + cb2 + cc) = v1;
            }
        }
    }
}

// =====================================================================
extern "C" void kernel_launch(void* const* d_in, const int* in_sizes, int n_in,
                              void* d_out, int out_size) {
    const float* z       = (const float*)d_in[0];
    const float* mask    = (const float*)d_in[1];
    const float* w_ab_p  = (const float*)d_in[2];
    const float* b_ab_p  = (const float*)d_in[3];
    const float* w_ab_g  = (const float*)d_in[4];
    const float* b_ab_g  = (const float*)d_in[5];
    const float* w_g     = (const float*)d_in[6];
    const float* b_g     = (const float*)d_in[7];
    const float* w_z     = (const float*)d_in[8];
    const float* b_z     = (const float*)d_in[9];
    const float* ln_in_g = (const float*)d_in[10];
    const float* ln_in_b = (const float*)d_in[11];
    const float* ln_out_g= (const float*)d_in[12];
    const float* ln_out_b= (const float*)d_in[13];
    float* out = (float*)d_out;

    cudaFuncSetAttribute(k1_mma,        cudaFuncAttributeMaxDynamicSharedMemorySize, K1_SMEM);
    cudaFuncSetAttribute(k2_einsum_mma, cudaFuncAttributeMaxDynamicSharedMemorySize, K2_SMEM);
    cudaFuncSetAttribute(k3_mma,        cudaFuncAttributeMaxDynamicSharedMemorySize, K3_SMEM);

    k0_wsplit<<<384, 256>>>(w_ab_g, w_ab_p, w_g, w_z);
    k1_mma<<<NR / 64, 256, K1_SMEM>>>(z, mask, b_ab_p, b_ab_g, b_g,
                                      ln_in_g, ln_in_b);
    k2_einsum_mma<<<dim3(4, 4, 128), 512, K2_SMEM>>>();
    k3_mma<<<NR / 64, 256, K3_SMEM>>>(b_z, ln_out_g, ln_out_b, out);
}

// round 14
// speedup vs baseline: 1.1617x; 1.1506x over previous
#include <cuda_runtime.h>
#include <cuda_fp16.h>
#include <math.h>
#include <cstdint>

#define NN   512
#define CZ   128
#define NR   (NN*NN)          // 262144
#define EPSV 1e-5f

// ---------------- scratch (device globals; alloc-free) ----------------
__device__ __half g_ah[(size_t)CZ * NR];   // a hi [c][i][k]
__device__ __half g_bh[(size_t)CZ * NR];   // b hi [c][j][k]
__device__ __half g_gate[(size_t)NR * CZ]; // gate[r][c]  (fp16)
__device__ __half g_x[(size_t)CZ * NR];    // x[c][i][j]  (fp16, L2-resident)
__device__ __half g_wH[768 * 128];         // packed weights hi [n][k]
__device__ __half g_wL[768 * 128];         // packed weights lo [n][k]

static __device__ __forceinline__ uint32_t smem_u32(const void* p) {
    return (uint32_t)__cvta_generic_to_shared(p);
}
static __device__ __forceinline__ void cp16(uint32_t dst, const void* src) {
    asm volatile("cp.async.cg.shared.global [%0], [%1], 16;" :: "r"(dst), "l"(src));
}
static __device__ __forceinline__ void cp_commit() {
    asm volatile("cp.async.commit_group;" ::: "memory");
}
static __device__ __forceinline__ void cp_wait1() {
    asm volatile("cp.async.wait_group 1;" ::: "memory");
}
static __device__ __forceinline__ void cp_wait0() {
    asm volatile("cp.async.wait_group 0;" ::: "memory");
}
static __device__ __forceinline__ void ldmx4(uint32_t* r, uint32_t addr) {
    asm volatile("ldmatrix.sync.aligned.m8n8.x4.shared.b16 {%0,%1,%2,%3}, [%4];"
                 : "=r"(r[0]), "=r"(r[1]), "=r"(r[2]), "=r"(r[3]) : "r"(addr));
}
static __device__ __forceinline__ void ldmx2(uint32_t* r, uint32_t addr) {
    asm volatile("ldmatrix.sync.aligned.m8n8.x2.shared.b16 {%0,%1}, [%2];"
                 : "=r"(r[0]), "=r"(r[1]) : "r"(addr));
}
static __device__ __forceinline__ void mma16816(float* d, const uint32_t* a, const uint32_t* b) {
    asm volatile("mma.sync.aligned.m16n8k16.row.col.f32.f16.f16.f32 "
                 "{%0,%1,%2,%3}, {%4,%5,%6,%7}, {%8,%9}, {%0,%1,%2,%3};"
                 : "+f"(d[0]), "+f"(d[1]), "+f"(d[2]), "+f"(d[3])
                 : "r"(a[0]), "r"(a[1]), "r"(a[2]), "r"(a[3]), "r"(b[0]), "r"(b[1]));
}

// =====================================================================
// Kernel 0: split weights into fp16 hi/lo, transposed to [n][k].
// n: 0-255 = w_ab_g, 256-511 = w_ab_p, 512-639 = w_g, 640-767 = w_z
// =====================================================================
__global__ void __launch_bounds__(256) k0_wsplit(
    const float* __restrict__ w_ab_g, const float* __restrict__ w_ab_p,
    const float* __restrict__ w_g,   const float* __restrict__ w_z)
{
    int idx = blockIdx.x * 256 + threadIdx.x;   // 384 blocks
    if (idx >= 768 * 128) return;
    int n = idx >> 7, k = idx & 127;
    float v;
    if (n < 256)      v = w_ab_g[k * 256 + n];
    else if (n < 512) v = w_ab_p[k * 256 + (n - 256)];
    else if (n < 640) v = w_g[k * 128 + (n - 512)];
    else              v = w_z[k * 128 + (n - 640)];
    __half h = __float2half(v);
    g_wH[idx] = h;
    g_wL[idx] = __float2half(v - __half2float(h));
}

// =====================================================================
// Kernel 1 (v6): LN(z) + projections, fp16 single-pass, G/P PAIRED.
// 4096 CTAs x 64 rows, 256 thr (8 warps: 2m x 4n), warp tile 32x16.
// 5 phases: 4x {Wg[64] + Wp[64]} -> a/b direct, 1x gate (128 cols).
// Double-buffered 34816-B W pairs. smem 87040 -> 2 CTAs/SM.
// =====================================================================
#define ASTR   136
#define OFF_AH 0                       // 17408 B
#define OFF_WB 17408                   // two 34816-B paired buffers
#define WBSZ   34816
#define K1_SMEM 87040

__global__ void __launch_bounds__(256, 2) k1_mma(
    const float* __restrict__ z, const float* __restrict__ mask,
    const float* __restrict__ b_ab_p, const float* __restrict__ b_ab_g,
    const float* __restrict__ b_g,
    const float* __restrict__ ln_g,  const float* __restrict__ ln_b)
{
    extern __shared__ char smem[];
    const uint32_t sbase = smem_u32(smem);
    const int t   = threadIdx.x;
    const int lid = t & 31;
    const int w   = t >> 5;
    const int wm  = w >> 2;
    const int wn  = w & 3;
    const int r0  = blockIdx.x * 64;

    // phase -> (tile0 row, tile1 row) in packed weights
    // ph 0..3: Wg[ph*64], Wp[256+ph*64]; ph4: gate halves 512, 576
    // ---- prefetch phase 0 into buffer 0 ----
    {
        #pragma unroll
        for (int p = 0; p < 4; ++p) {
            int idx = p * 256 + t;
            int n = idx >> 4, seg = idx & 15;
            cp16(sbase + OFF_WB + n * 272 + seg * 16,
                 g_wH + (size_t)n * 128 + seg * 8);
            cp16(sbase + OFF_WB + 17408 + n * 272 + seg * 16,
                 g_wH + (size_t)(256 + n) * 128 + seg * 8);
        }
        cp_commit();
    }

    // ---- z via LDG -> LN (4 thr/row, shfl) -> fp16 hi smem ----
    {
        const int row = t >> 2, qt = t & 3;
        const float4* zr = (const float4*)(z + (size_t)(r0 + row) * CZ + qt * 32);
        float4 v[8];
        #pragma unroll
        for (int q = 0; q < 8; ++q) v[q] = __ldg(zr + q);
        float s = 0.f, s2 = 0.f;
        #pragma unroll
        for (int q = 0; q < 8; ++q) {
            s  += v[q].x + v[q].y + v[q].z + v[q].w;
            s2 += v[q].x*v[q].x + v[q].y*v[q].y + v[q].z*v[q].z + v[q].w*v[q].w;
        }
        s  += __shfl_xor_sync(0xffffffffu, s, 1);
        s2 += __shfl_xor_sync(0xffffffffu, s2, 1);
        s  += __shfl_xor_sync(0xffffffffu, s, 2);
        s2 += __shfl_xor_sync(0xffffffffu, s2, 2);
        float mu  = s * (1.0f/128.0f);
        float var = fmaxf(s2 * (1.0f/128.0f) - mu*mu, 0.f);
        float rs  = rsqrtf(var + EPSV);

        __half* aH = (__half*)(smem + OFF_AH) + row * ASTR + qt * 32;
        #pragma unroll
        for (int q8 = 0; q8 < 4; ++q8) {
            const float vv[8] = {v[q8*2].x, v[q8*2].y, v[q8*2].z, v[q8*2].w,
                                 v[q8*2+1].x, v[q8*2+1].y, v[q8*2+1].z, v[q8*2+1].w};
            __align__(16) __half hb[8];
            #pragma unroll
            for (int j = 0; j < 8; ++j) {
                int c = qt * 32 + q8 * 8 + j;
                hb[j] = __float2half((vv[j] - mu) * rs * __ldg(ln_g + c) + __ldg(ln_b + c));
            }
            *(uint4*)(aH + q8*8) = *(uint4*)hb;
        }
    }

    const int quad = lid >> 3;
    const int l7   = lid & 7;
    uint32_t aoff[2];
    #pragma unroll
    for (int mf = 0; mf < 2; ++mf) {
        int r = wm*32 + mf*16 + (quad & 1)*8 + l7;
        aoff[mf] = (r * ASTR + (quad >> 1) * 8) * 2;
    }
    const uint32_t boff = ((wn*16 + (quad & 1)*8 + l7) * ASTR + (quad >> 1) * 8) * 2;
    const int rbase = wm*32 + (lid >> 2);
    const int cbase_w = wn*16 + (lid & 3)*2;

    for (int ph = 0; ph < 5; ++ph) {
        __syncthreads();   // A visible (ph0); prior staging reads done
        const uint32_t wb = sbase + OFF_WB + (ph & 1) * WBSZ;
        if (ph < 4) {
            const uint32_t wbn = sbase + OFF_WB + ((ph + 1) & 1) * WBSZ;
            const int t0 = (ph + 1 < 4) ? (ph + 1) * 64 : 512;
            const int t1 = (ph + 1 < 4) ? 256 + (ph + 1) * 64 : 576;
            #pragma unroll
            for (int p = 0; p < 4; ++p) {
                int idx = p * 256 + t;
                int n = idx >> 4, seg = idx & 15;
                cp16(wbn + n * 272 + seg * 16,
                     g_wH + (size_t)(t0 + n) * 128 + seg * 8);
                cp16(wbn + 17408 + n * 272 + seg * 16,
                     g_wH + (size_t)(t1 + n) * 128 + seg * 8);
            }
            cp_commit();
            cp_wait1();
        } else {
            cp_wait0();
        }
        __syncthreads();

        float accG[2][2][4], accP[2][2][4];
        #pragma unroll
        for (int mf = 0; mf < 2; ++mf)
            #pragma unroll
            for (int nf = 0; nf < 2; ++nf)
                #pragma unroll
                for (int q = 0; q < 4; ++q) { accG[mf][nf][q] = 0.f; accP[mf][nf][q] = 0.f; }

        #pragma unroll
        for (int ks = 0; ks < 128; ks += 16) {
            uint32_t ah[2][4], bg2[2][2], bp2[2][2], r4[4];
            ldmx4(ah[0], sbase + OFF_AH + aoff[0] + ks*2);
            ldmx4(ah[1], sbase + OFF_AH + aoff[1] + ks*2);
            ldmx4(r4, wb + boff + ks*2);
            bg2[0][0] = r4[0]; bg2[0][1] = r4[2];
            bg2[1][0] = r4[1]; bg2[1][1] = r4[3];
            ldmx4(r4, wb + 17408 + boff + ks*2);
            bp2[0][0] = r4[0]; bp2[0][1] = r4[2];
            bp2[1][0] = r4[1]; bp2[1][1] = r4[3];
            #pragma unroll
            for (int mf = 0; mf < 2; ++mf)
                #pragma unroll
                for (int nf = 0; nf < 2; ++nf)
                    mma16816(accG[mf][nf], ah[mf], bg2[nf]);
            #pragma unroll
            for (int mf = 0; mf < 2; ++mf)
                #pragma unroll
                for (int nf = 0; nf < 2; ++nf)
                    mma16816(accP[mf][nf], ah[mf], bp2[nf]);
        }

        if (ph == 4) {
            // gate phase: accG -> cols 0..63, accP -> cols 64..127
            #pragma unroll
            for (int mf = 0; mf < 2; ++mf) {
                int rr0 = rbase + mf*16, rr1 = rr0 + 8;
                #pragma unroll
                for (int nf = 0; nf < 2; ++nf) {
                    int cc = cbase_w + nf*8;
                    float g0 = __ldg(b_g + cc),       g1 = __ldg(b_g + cc + 1);
                    float g2 = __ldg(b_g + 64 + cc),  g3 = __ldg(b_g + 64 + cc + 1);
                    __half2 hA0, hA1, hB0, hB1;
                    hA0.x = __float2half(1.f/(1.f + __expf(-(accG[mf][nf][0] + g0))));
                    hA0.y = __float2half(1.f/(1.f + __expf(-(accG[mf][nf][1] + g1))));
                    hA1.x = __float2half(1.f/(1.f + __expf(-(accG[mf][nf][2] + g0))));
                    hA1.y = __float2half(1.f/(1.f + __expf(-(accG[mf][nf][3] + g1))));
                    hB0.x = __float2half(1.f/(1.f + __expf(-(accP[mf][nf][0] + g2))));
                    hB0.y = __float2half(1.f/(1.f + __expf(-(accP[mf][nf][1] + g3))));
                    hB1.x = __float2half(1.f/(1.f + __expf(-(accP[mf][nf][2] + g2))));
                    hB1.y = __float2half(1.f/(1.f + __expf(-(accP[mf][nf][3] + g3))));
                    *(__half2*)(g_gate + (size_t)(r0 + rr0) * CZ + cc)      = hA0;
                    *(__half2*)(g_gate + (size_t)(r0 + rr1) * CZ + cc)      = hA1;
                    *(__half2*)(g_gate + (size_t)(r0 + rr0) * CZ + 64 + cc) = hB0;
                    *(__half2*)(g_gate + (size_t)(r0 + rr1) * CZ + 64 + cc) = hB1;
                }
            }
        } else {
            // ab phase: v = mask * sigmoid(G+bg) * (P+bp); stage into dead wb
            const float* bgp = b_ab_g + ph * 64;
            const float* bpp = b_ab_p + ph * 64;
            __syncthreads();   // all warps done reading wb via ldmatrix
            uint32_t* stg = (uint32_t*)(smem + OFF_WB + (ph & 1) * WBSZ);
            #pragma unroll
            for (int mf = 0; mf < 2; ++mf) {
                int rr0 = rbase + mf*16, rr1 = rr0 + 8;
                float m0 = __ldg(mask + r0 + rr0);
                float m1 = __ldg(mask + r0 + rr1);
                #pragma unroll
                for (int nf = 0; nf < 2; ++nf) {
                    int cc = cbase_w + nf*8;
                    float bg0 = __ldg(bgp + cc), bg1 = __ldg(bgp + cc + 1);
                    float bp0 = __ldg(bpp + cc), bp1 = __ldg(bpp + cc + 1);
                    float s00 = 1.f/(1.f + __expf(-(accG[mf][nf][0] + bg0)));
                    float s01 = 1.f/(1.f + __expf(-(accG[mf][nf][1] + bg1)));
                    float s10 = 1.f/(1.f + __expf(-(accG[mf][nf][2] + bg0)));
                    float s11 = 1.f/(1.f + __expf(-(accG[mf][nf][3] + bg1)));
                    stg[cc*68 + rr0]     = (uint32_t)__half_as_ushort(
                        __float2half(m0 * s00 * (accP[mf][nf][0] + bp0)));
                    stg[(cc+1)*68 + rr0] = (uint32_t)__half_as_ushort(
                        __float2half(m0 * s01 * (accP[mf][nf][1] + bp1)));
                    stg[cc*68 + rr1]     = (uint32_t)__half_as_ushort(
                        __float2half(m1 * s10 * (accP[mf][nf][2] + bp0)));
                    stg[(cc+1)*68 + rr1] = (uint32_t)__half_as_ushort(
                        __float2half(m1 * s11 * (accP[mf][nf][3] + bp1)));
                }
            }
            __syncthreads();
            __half* dH = (ph < 2) ? g_ah : g_bh;
            const int cch = (ph & 1) * 64 + (t >> 2);
            const int rrb = (t & 3) * 16;
            size_t off = (size_t)cch * NR + r0 + rrb;
            const uint32_t* sp = stg + (t >> 2) * 68 + rrb;
            __align__(16) unsigned short hb[16];
            #pragma unroll
            for (int i = 0; i < 16; ++i) hb[i] = (unsigned short)(sp[i] & 0xffffu);
            *(uint4*)(dH + off)     = *(uint4*)(hb);
            *(uint4*)(dH + off + 8) = *(uint4*)(hb + 8);
        }
    }
}

// =====================================================================
// Kernel 2 (v4): einsum fp16 single-pass; X written fp16 (unchanged).
// =====================================================================
#define KC     32
#define STR    40
#define TILE_E (128*STR)
#define BUF_E  (2*TILE_E)
#define K2_SMEM (2 * BUF_E * 2)         // 40960

__global__ void __launch_bounds__(512) k2_einsum_mma() {
    extern __shared__ __half sb[];
    const uint32_t sbase = smem_u32(sb);

    const int t   = threadIdx.x;
    const int lid = t & 31;
    const int w   = t >> 5;
    const int wm  = w >> 2;
    const int wn  = w & 3;
    const int c   = blockIdx.z;
    const int m0  = blockIdx.y * 128;
    const int n0  = blockIdx.x * 128;

    const __half* pAh = g_ah + (size_t)c * NR;
    const __half* pBh = g_bh + (size_t)c * NR;

    const int grow = t >> 2;
    const int gseg = t & 3;
    const size_t gA0 = (size_t)(m0 + grow) * NN + gseg * 8;
    const size_t gB0 = (size_t)(n0 + grow) * NN + gseg * 8;
    const uint32_t sw = (grow * STR + gseg * 8) * 2;

    const int quad = lid >> 3;
    const int l7   = lid & 7;
    uint32_t aoff[2];
    #pragma unroll
    for (int mf = 0; mf < 2; ++mf) {
        int r = wm*32 + mf*16 + (quad & 1)*8 + l7;
        aoff[mf] = (r * STR + (quad >> 1) * 8) * 2;
    }
    uint32_t boff[4];
    #pragma unroll
    for (int nf = 0; nf < 4; ++nf) {
        int r = wn*32 + nf*8 + l7;
        boff[nf] = (r * STR + ((lid >> 3) & 1) * 8) * 2;
    }

    float d[2][4][4];
    #pragma unroll
    for (int mf = 0; mf < 2; ++mf)
        #pragma unroll
        for (int nf = 0; nf < 4; ++nf)
            #pragma unroll
            for (int q = 0; q < 4; ++q) d[mf][nf][q] = 0.f;

    {
        uint32_t b0 = sbase;
        cp16(b0 + 0*TILE_E*2 + sw, pAh + gA0);
        cp16(b0 + 1*TILE_E*2 + sw, pBh + gB0);
        cp_commit();
    }

    for (int ch = 0; ch < 16; ++ch) {
        if (ch < 15) {
            uint32_t bb = sbase + ((ch + 1) & 1) * BUF_E * 2;
            int kk = (ch + 1) * KC;
            cp16(bb + 0*TILE_E*2 + sw, pAh + gA0 + kk);
            cp16(bb + 1*TILE_E*2 + sw, pBh + gB0 + kk);
            cp_commit();
            cp_wait1();
        } else {
            cp_wait0();
        }
        __syncthreads();

        const uint32_t bb = sbase + (ch & 1) * BUF_E * 2;
        const uint32_t bAH = bb;
        const uint32_t bBH = bb + TILE_E*2;

        #pragma unroll
        for (int ks = 0; ks < KC; ks += 16) {
            uint32_t ah[2][4], bh[4][2];
            #pragma unroll
            for (int mf = 0; mf < 2; ++mf) ldmx4(ah[mf], bAH + aoff[mf] + ks*2);
            #pragma unroll
            for (int nf = 0; nf < 4; ++nf) ldmx2(bh[nf], bBH + boff[nf] + ks*2);
            #pragma unroll
            for (int mf = 0; mf < 2; ++mf)
                #pragma unroll
                for (int nf = 0; nf < 4; ++nf)
                    mma16816(d[mf][nf], ah[mf], bh[nf]);
        }
        __syncthreads();
    }

    __half* X = g_x + (size_t)c * NR;
    const int rb = m0 + wm*32 + (lid >> 2);
    const int cb = n0 + wn*32 + (lid & 3) * 2;
    #pragma unroll
    for (int mf = 0; mf < 2; ++mf)
        #pragma unroll
        for (int nf = 0; nf < 4; ++nf) {
            int row = rb + mf*16;
            int col = cb + nf*8;
            *(__half2*)(X + (size_t)row * NN + col) =
                __floats2half2_rn(d[mf][nf][0], d[mf][nf][1]);
            *(__half2*)(X + (size_t)(row + 8) * NN + col) =
                __floats2half2_rn(d[mf][nf][2], d[mf][nf][3]);
        }
}

// =====================================================================
// Kernel 3 (v6): gather x (fp16) -> LN (reg-buffered) -> @ w_z (3-pass)
// -> *gate -> out.  AH/AL OVERLAY the gather staging; smem 69632 ->
// 3 CTAs/SM. W chunk 0 prefetched before gather.
// =====================================================================
#define K3_AH 0
#define K3_AL 17408
#define K3_WH 34816
#define K3_WL 52224
#define K3_SMEM 69632

__global__ void __launch_bounds__(256, 3) k3_mma(
    const float* __restrict__ b_z,
    const float* __restrict__ ln_g, const float* __restrict__ ln_b,
    float* __restrict__ out)
{
    extern __shared__ char smem[];
    const uint32_t sbase = smem_u32(smem);
    float* xS = (float*)smem;                    // [row][c] stride 132 (33792 B)
    const int t   = threadIdx.x;
    const int lid = t & 31;
    const int w   = t >> 5;
    const int wm  = w >> 2;
    const int wn  = w & 3;
    const int r0  = blockIdx.x * 64;
    const int i0  = r0 >> 9;
    const int j0  = r0 & 511;

    // prefetch W chunk 0 (overlaps gather)
    {
        #pragma unroll
        for (int p = 0; p < 4; ++p) {
            int idx = p * 256 + t;
            int n = idx >> 4, seg = idx & 15;
            cp16(sbase + K3_WH + n * 272 + seg * 16,
                 g_wH + (size_t)(640 + n) * 128 + seg * 8);
            cp16(sbase + K3_WL + n * 272 + seg * 16,
                 g_wL + (size_t)(640 + n) * 128 + seg * 8);
        }
        cp_commit();
    }

    // gather x (fp16 c-major) -> fp32 staging
    {
        const int joff = t & 63, part = t >> 6;
        const __half* src = g_x + (size_t)(part*32) * NR + (size_t)i0 * NN + j0 + joff;
        #pragma unroll
        for (int q = 0; q < 32; ++q)
            xS[joff*132 + part*32 + q] = __half2float(src[(size_t)q * NR]);
    }
    __syncthreads();

    // LN into registers (packed hi/lo), then overwrite staging with AH/AL
    {
        const int row = t >> 2, qt = t & 3;
        const float* zr = xS + row * 132 + qt * 32;
        float vbuf[32];
        float s = 0.f, s2 = 0.f;
        #pragma unroll
        for (int q = 0; q < 8; ++q) {
            float4 v = *(const float4*)(zr + q * 4);
            vbuf[q*4+0] = v.x; vbuf[q*4+1] = v.y; vbuf[q*4+2] = v.z; vbuf[q*4+3] = v.w;
            s  += v.x + v.y + v.z + v.w;
            s2 += v.x*v.x + v.y*v.y + v.z*v.z + v.w*v.w;
        }
        s  += __shfl_xor_sync(0xffffffffu, s, 1);
        s2 += __shfl_xor_sync(0xffffffffu, s2, 1);
        s  += __shfl_xor_sync(0xffffffffu, s, 2);
        s2 += __shfl_xor_sync(0xffffffffu, s2, 2);
        float mu  = s * (1.0f/128.0f);
        float var = fmaxf(s2 * (1.0f/128.0f) - mu*mu, 0.f);
        float rs  = rsqrtf(var + EPSV);

        __align__(16) __half hb[32], lb[32];
        #pragma unroll
        for (int j = 0; j < 32; ++j) {
            int c = qt * 32 + j;
            float v = (vbuf[j] - mu) * rs * __ldg(ln_g + c) + __ldg(ln_b + c);
            __half h = __float2half(v);
            hb[j] = h;
            lb[j] = __float2half(v - __half2float(h));
        }
        __syncthreads();   // all xS reads complete before overlay writes
        __half* aH = (__half*)(smem + K3_AH) + row * ASTR + qt * 32;
        __half* aL = (__half*)(smem + K3_AL) + row * ASTR + qt * 32;
        #pragma unroll
        for (int q8 = 0; q8 < 4; ++q8) {
            *(uint4*)(aH + q8*8) = *(uint4*)(hb + q8*8);
            *(uint4*)(aL + q8*8) = *(uint4*)(lb + q8*8);
        }
    }

    const int quad = lid >> 3;
    const int l7   = lid & 7;
    uint32_t aoff[2];
    #pragma unroll
    for (int mf = 0; mf < 2; ++mf) {
        int r = wm*32 + mf*16 + (quad & 1)*8 + l7;
        aoff[mf] = (r * ASTR + (quad >> 1) * 8) * 2;
    }
    const uint32_t boff = ((wn*16 + (quad & 1)*8 + l7) * ASTR + (quad >> 1) * 8) * 2;
    const int rbase = wm*32 + (lid >> 2);
    const int cbase_w = wn*16 + (lid & 3)*2;

    for (int ci = 0; ci < 2; ++ci) {
        __syncthreads();
        if (ci == 1) {
            #pragma unroll
            for (int p = 0; p < 4; ++p) {
                int idx = p * 256 + t;
                int n = idx >> 4, seg = idx & 15;
                cp16(sbase + K3_WH + n * 272 + seg * 16,
                     g_wH + (size_t)(704 + n) * 128 + seg * 8);
                cp16(sbase + K3_WL + n * 272 + seg * 16,
                     g_wL + (size_t)(704 + n) * 128 + seg * 8);
            }
            cp_commit();
        }
        cp_wait0();
        __syncthreads();

        float acc[2][2][4];
        #pragma unroll
        for (int mf = 0; mf < 2; ++mf)
            #pragma unroll
            for (int nf = 0; nf < 2; ++nf)
                #pragma unroll
                for (int q = 0; q < 4; ++q) acc[mf][nf][q] = 0.f;

        #pragma unroll
        for (int ks = 0; ks < 128; ks += 16) {
            uint32_t ah[2][4], al[2][4], bh[2][2], bl[2][2], r4[4];
            ldmx4(ah[0], sbase + K3_AH + aoff[0] + ks*2);
            ldmx4(ah[1], sbase + K3_AH + aoff[1] + ks*2);
            ldmx4(al[0], sbase + K3_AL + aoff[0] + ks*2);
            ldmx4(al[1], sbase + K3_AL + aoff[1] + ks*2);
            ldmx4(r4, sbase + K3_WH + boff + ks*2);
            bh[0][0] = r4[0]; bh[0][1] = r4[2];
            bh[1][0] = r4[1]; bh[1][1] = r4[3];
            ldmx4(r4, sbase + K3_WL + boff + ks*2);
            bl[0][0] = r4[0]; bl[0][1] = r4[2];
            bl[1][0] = r4[1]; bl[1][1] = r4[3];
            #pragma unroll
            for (int mf = 0; mf < 2; ++mf)
                #pragma unroll
                for (int nf = 0; nf < 2; ++nf)
                    mma16816(acc[mf][nf], ah[mf], bh[nf]);
            #pragma unroll
            for (int mf = 0; mf < 2; ++mf)
                #pragma unroll
                for (int nf = 0; nf < 2; ++nf)
                    mma16816(acc[mf][nf], ah[mf], bl[nf]);
            #pragma unroll
            for (int mf = 0; mf < 2; ++mf)
                #pragma unroll
                for (int nf = 0; nf < 2; ++nf)
                    mma16816(acc[mf][nf], al[mf], bh[nf]);
        }

        const int cb2 = ci * 64;
        #pragma unroll
        for (int mf = 0; mf < 2; ++mf) {
            int rr0 = rbase + mf*16, rr1 = rr0 + 8;
            #pragma unroll
            for (int nf = 0; nf < 2; ++nf) {
                int cc = cbase_w + nf*8;
                float b0 = __ldg(b_z + cb2 + cc);
                float b1 = __ldg(b_z + cb2 + cc + 1);
                float2 gg0 = __half22float2(*(const __half2*)(g_gate + (size_t)(r0 + rr0) * CZ + cb2 + cc));
                float2 gg1 = __half22float2(*(const __half2*)(g_gate + (size_t)(r0 + rr1) * CZ + cb2 + cc));
                float2 v0, v1;
                v0.x = (acc[mf][nf][0] + b0) * gg0.x;
                v0.y = (acc[mf][nf][1] + b1) * gg0.y;
                v1.x = (acc[mf][nf][2] + b0) * gg1.x;
                v1.y = (acc[mf][nf][3] + b1) * gg1.y;
                *(float2*)(out + (size_t)(r0 + rr0) * CZ + cb2 + cc) = v0;
                *(float2*)(out + (size_t)(r0 + rr1) * CZ + cb2 + cc) = v1;
            }
        }
    }
}

// =====================================================================
extern "C" void kernel_launch(void* const* d_in, const int* in_sizes, int n_in,
                              void* d_out, int out_size) {
    const float* z       = (const float*)d_in[0];
    const float* mask    = (const float*)d_in[1];
    const float* w_ab_p  = (const float*)d_in[2];
    const float* b_ab_p  = (const float*)d_in[3];
    const float* w_ab_g  = (const float*)d_in[4];
    const float* b_ab_g  = (const float*)d_in[5];
    const float* w_g     = (const float*)d_in[6];
    const float* b_g     = (const float*)d_in[7];
    const float* w_z     = (const float*)d_in[8];
    const float* b_z     = (const float*)d_in[9];
    const float* ln_in_g = (const float*)d_in[10];
    const float* ln_in_b = (const float*)d_in[11];
    const float* ln_out_g= (const float*)d_in[12];
    const float* ln_out_b= (const float*)d_in[13];
    float* out = (float*)d_out;

    cudaFuncSetAttribute(k1_mma,        cudaFuncAttributeMaxDynamicSharedMemorySize, K1_SMEM);
    cudaFuncSetAttribute(k2_einsum_mma, cudaFuncAttributeMaxDynamicSharedMemorySize, K2_SMEM);
    cudaFuncSetAttribute(k3_mma,        cudaFuncAttributeMaxDynamicSharedMemorySize, K3_SMEM);

    k0_wsplit<<<384, 256>>>(w_ab_g, w_ab_p, w_g, w_z);
    k1_mma<<<NR / 64, 256, K1_SMEM>>>(z, mask, b_ab_p, b_ab_g, b_g,
                                      ln_in_g, ln_in_b);
    k2_einsum_mma<<<dim3(4, 4, 128), 512, K2_SMEM>>>();
    k3_mma<<<NR / 64, 256, K3_SMEM>>>(b_z, ln_out_g, ln_out_b, out);
}

// round 15
// speedup vs baseline: 1.2660x; 1.0898x over previous
#include <cuda_runtime.h>
#include <cuda_fp16.h>
#include <math.h>
#include <cstdint>

#define NN   512
#define CZ   128
#define NR   (NN*NN)          // 262144
#define EPSV 1e-5f

// ---------------- scratch (device globals; alloc-free) ----------------
__device__ __half g_ah[(size_t)CZ * NR];   // a hi [c][i][k]
__device__ __half g_bh[(size_t)CZ * NR];   // b hi [c][j][k]
__device__ __half g_gate[(size_t)NR * CZ]; // gate[r][c]  (fp16)
__device__ __half g_x[(size_t)CZ * NR];    // x[c][i][j]  (fp16, L2-resident)
__device__ __half g_wH[768 * 128];         // packed weights hi [n][k]
__device__ __half g_wL[768 * 128];         // packed weights lo [n][k]

static __device__ __forceinline__ uint32_t smem_u32(const void* p) {
    return (uint32_t)__cvta_generic_to_shared(p);
}
static __device__ __forceinline__ void cp16(uint32_t dst, const void* src) {
    asm volatile("cp.async.cg.shared.global [%0], [%1], 16;" :: "r"(dst), "l"(src));
}
static __device__ __forceinline__ void cp_commit() {
    asm volatile("cp.async.commit_group;" ::: "memory");
}
static __device__ __forceinline__ void cp_wait0() {
    asm volatile("cp.async.wait_group 0;" ::: "memory");
}
static __device__ __forceinline__ void ldmx4(uint32_t* r, uint32_t addr) {
    asm volatile("ldmatrix.sync.aligned.m8n8.x4.shared.b16 {%0,%1,%2,%3}, [%4];"
                 : "=r"(r[0]), "=r"(r[1]), "=r"(r[2]), "=r"(r[3]) : "r"(addr));
}
static __device__ __forceinline__ void ldmx2(uint32_t* r, uint32_t addr) {
    asm volatile("ldmatrix.sync.aligned.m8n8.x2.shared.b16 {%0,%1}, [%2];"
                 : "=r"(r[0]), "=r"(r[1]) : "r"(addr));
}
static __device__ __forceinline__ void mma16816(float* d, const uint32_t* a, const uint32_t* b) {
    asm volatile("mma.sync.aligned.m16n8k16.row.col.f32.f16.f16.f32 "
                 "{%0,%1,%2,%3}, {%4,%5,%6,%7}, {%8,%9}, {%0,%1,%2,%3};"
                 : "+f"(d[0]), "+f"(d[1]), "+f"(d[2]), "+f"(d[3])
                 : "r"(a[0]), "r"(a[1]), "r"(a[2]), "r"(a[3]), "r"(b[0]), "r"(b[1]));
}

// =====================================================================
// Kernel 0: split weights into fp16 hi/lo, transposed to [n][k].
// n: 0-255 = w_ab_g, 256-511 = w_ab_p, 512-639 = w_g, 640-767 = w_z
// =====================================================================
__global__ void __launch_bounds__(256) k0_wsplit(
    const float* __restrict__ w_ab_g, const float* __restrict__ w_ab_p,
    const float* __restrict__ w_g,   const float* __restrict__ w_z)
{
    int idx = blockIdx.x * 256 + threadIdx.x;   // 384 blocks
    if (idx >= 768 * 128) return;
    int n = idx >> 7, k = idx & 127;
    float v;
    if (n < 256)      v = w_ab_g[k * 256 + n];
    else if (n < 512) v = w_ab_p[k * 256 + (n - 256)];
    else if (n < 640) v = w_g[k * 128 + (n - 512)];
    else              v = w_z[k * 128 + (n - 640)];
    __half h = __float2half(v);
    g_wH[idx] = h;
    g_wL[idx] = __float2half(v - __half2float(h));
}

// =====================================================================
// Kernel 1 (v7): LN(z) + projections, fp16 single-pass, G/P paired.
// SINGLE W buffer, smem 52224 -> 3 CTAs/SM (occupancy hides W loads).
// 4096 CTAs x 64 rows, 256 thr (8 warps: 2m x 4n), warp tile 32x16.
// =====================================================================
#define ASTR   136
#define OFF_AH 0                       // 17408 B
#define OFF_WG 17408                   // 17408 B (Wg chunk; also P staging)
#define OFF_WP 34816                   // 17408 B (Wp chunk)
#define K1_SMEM 52224

__global__ void __launch_bounds__(256, 3) k1_mma(
    const float* __restrict__ z, const float* __restrict__ mask,
    const float* __restrict__ b_ab_p, const float* __restrict__ b_ab_g,
    const float* __restrict__ b_g,
    const float* __restrict__ ln_g,  const float* __restrict__ ln_b)
{
    extern __shared__ char smem[];
    const uint32_t sbase = smem_u32(smem);
    const int t   = threadIdx.x;
    const int lid = t & 31;
    const int w   = t >> 5;
    const int wm  = w >> 2;
    const int wn  = w & 3;
    const int r0  = blockIdx.x * 64;

    // ---- prefetch phase-0 W pair (overlaps z load + LN) ----
    {
        #pragma unroll
        for (int p = 0; p < 4; ++p) {
            int idx = p * 256 + t;
            int n = idx >> 4, seg = idx & 15;
            cp16(sbase + OFF_WG + n * 272 + seg * 16,
                 g_wH + (size_t)n * 128 + seg * 8);
            cp16(sbase + OFF_WP + n * 272 + seg * 16,
                 g_wH + (size_t)(256 + n) * 128 + seg * 8);
        }
        cp_commit();
    }

    // ---- z via LDG -> LN (4 thr/row, shfl) -> fp16 hi smem ----
    {
        const int row = t >> 2, qt = t & 3;
        const float4* zr = (const float4*)(z + (size_t)(r0 + row) * CZ + qt * 32);
        float4 v[8];
        #pragma unroll
        for (int q = 0; q < 8; ++q) v[q] = __ldg(zr + q);
        float s = 0.f, s2 = 0.f;
        #pragma unroll
        for (int q = 0; q < 8; ++q) {
            s  += v[q].x + v[q].y + v[q].z + v[q].w;
            s2 += v[q].x*v[q].x + v[q].y*v[q].y + v[q].z*v[q].z + v[q].w*v[q].w;
        }
        s  += __shfl_xor_sync(0xffffffffu, s, 1);
        s2 += __shfl_xor_sync(0xffffffffu, s2, 1);
        s  += __shfl_xor_sync(0xffffffffu, s, 2);
        s2 += __shfl_xor_sync(0xffffffffu, s2, 2);
        float mu  = s * (1.0f/128.0f);
        float var = fmaxf(s2 * (1.0f/128.0f) - mu*mu, 0.f);
        float rs  = rsqrtf(var + EPSV);

        __half* aH = (__half*)(smem + OFF_AH) + row * ASTR + qt * 32;
        #pragma unroll
        for (int q8 = 0; q8 < 4; ++q8) {
            const float vv[8] = {v[q8*2].x, v[q8*2].y, v[q8*2].z, v[q8*2].w,
                                 v[q8*2+1].x, v[q8*2+1].y, v[q8*2+1].z, v[q8*2+1].w};
            __align__(16) __half hb[8];
            #pragma unroll
            for (int j = 0; j < 8; ++j) {
                int c = qt * 32 + q8 * 8 + j;
                hb[j] = __float2half((vv[j] - mu) * rs * __ldg(ln_g + c) + __ldg(ln_b + c));
            }
            *(uint4*)(aH + q8*8) = *(uint4*)hb;
        }
    }

    const int quad = lid >> 3;
    const int l7   = lid & 7;
    uint32_t aoff[2];
    #pragma unroll
    for (int mf = 0; mf < 2; ++mf) {
        int r = wm*32 + mf*16 + (quad & 1)*8 + l7;
        aoff[mf] = (r * ASTR + (quad >> 1) * 8) * 2;
    }
    const uint32_t boff = ((wn*16 + (quad & 1)*8 + l7) * ASTR + (quad >> 1) * 8) * 2;
    const int rbase = wm*32 + (lid >> 2);
    const int cbase_w = wn*16 + (lid & 3)*2;

    for (int ph = 0; ph < 5; ++ph) {
        __syncthreads();   // A visible (ph0); prior staging/W reads done
        if (ph > 0) {
            const int t0 = (ph < 4) ? ph * 64 : 512;
            const int t1 = (ph < 4) ? 256 + ph * 64 : 576;
            #pragma unroll
            for (int p = 0; p < 4; ++p) {
                int idx = p * 256 + t;
                int n = idx >> 4, seg = idx & 15;
                cp16(sbase + OFF_WG + n * 272 + seg * 16,
                     g_wH + (size_t)(t0 + n) * 128 + seg * 8);
                cp16(sbase + OFF_WP + n * 272 + seg * 16,
                     g_wH + (size_t)(t1 + n) * 128 + seg * 8);
            }
            cp_commit();
        }
        cp_wait0();
        __syncthreads();

        float accG[2][2][4], accP[2][2][4];
        #pragma unroll
        for (int mf = 0; mf < 2; ++mf)
            #pragma unroll
            for (int nf = 0; nf < 2; ++nf)
                #pragma unroll
                for (int q = 0; q < 4; ++q) { accG[mf][nf][q] = 0.f; accP[mf][nf][q] = 0.f; }

        #pragma unroll
        for (int ks = 0; ks < 128; ks += 16) {
            uint32_t ah[2][4], bg2[2][2], bp2[2][2], r4[4];
            ldmx4(ah[0], sbase + OFF_AH + aoff[0] + ks*2);
            ldmx4(ah[1], sbase + OFF_AH + aoff[1] + ks*2);
            ldmx4(r4, sbase + OFF_WG + boff + ks*2);
            bg2[0][0] = r4[0]; bg2[0][1] = r4[2];
            bg2[1][0] = r4[1]; bg2[1][1] = r4[3];
            ldmx4(r4, sbase + OFF_WP + boff + ks*2);
            bp2[0][0] = r4[0]; bp2[0][1] = r4[2];
            bp2[1][0] = r4[1]; bp2[1][1] = r4[3];
            #pragma unroll
            for (int mf = 0; mf < 2; ++mf)
                #pragma unroll
                for (int nf = 0; nf < 2; ++nf)
                    mma16816(accG[mf][nf], ah[mf], bg2[nf]);
            #pragma unroll
            for (int mf = 0; mf < 2; ++mf)
                #pragma unroll
                for (int nf = 0; nf < 2; ++nf)
                    mma16816(accP[mf][nf], ah[mf], bp2[nf]);
        }

        if (ph == 4) {
            // gate phase: accG -> cols 0..63, accP -> cols 64..127
            #pragma unroll
            for (int mf = 0; mf < 2; ++mf) {
                int rr0 = rbase + mf*16, rr1 = rr0 + 8;
                #pragma unroll
                for (int nf = 0; nf < 2; ++nf) {
                    int cc = cbase_w + nf*8;
                    float g0 = __ldg(b_g + cc),       g1 = __ldg(b_g + cc + 1);
                    float g2 = __ldg(b_g + 64 + cc),  g3 = __ldg(b_g + 64 + cc + 1);
                    __half2 hA0, hA1, hB0, hB1;
                    hA0.x = __float2half(1.f/(1.f + __expf(-(accG[mf][nf][0] + g0))));
                    hA0.y = __float2half(1.f/(1.f + __expf(-(accG[mf][nf][1] + g1))));
                    hA1.x = __float2half(1.f/(1.f + __expf(-(accG[mf][nf][2] + g0))));
                    hA1.y = __float2half(1.f/(1.f + __expf(-(accG[mf][nf][3] + g1))));
                    hB0.x = __float2half(1.f/(1.f + __expf(-(accP[mf][nf][0] + g2))));
                    hB0.y = __float2half(1.f/(1.f + __expf(-(accP[mf][nf][1] + g3))));
                    hB1.x = __float2half(1.f/(1.f + __expf(-(accP[mf][nf][2] + g2))));
                    hB1.y = __float2half(1.f/(1.f + __expf(-(accP[mf][nf][3] + g3))));
                    *(__half2*)(g_gate + (size_t)(r0 + rr0) * CZ + cc)      = hA0;
                    *(__half2*)(g_gate + (size_t)(r0 + rr1) * CZ + cc)      = hA1;
                    *(__half2*)(g_gate + (size_t)(r0 + rr0) * CZ + 64 + cc) = hB0;
                    *(__half2*)(g_gate + (size_t)(r0 + rr1) * CZ + 64 + cc) = hB1;
                }
            }
        } else {
            // ab phase: v = mask * sigmoid(G+bg) * (P+bp); stage into dead WG
            const float* bgp = b_ab_g + ph * 64;
            const float* bpp = b_ab_p + ph * 64;
            __syncthreads();   // all warps done reading W via ldmatrix
            uint32_t* stg = (uint32_t*)(smem + OFF_WG);
            #pragma unroll
            for (int mf = 0; mf < 2; ++mf) {
                int rr0 = rbase + mf*16, rr1 = rr0 + 8;
                float m0 = __ldg(mask + r0 + rr0);
                float m1 = __ldg(mask + r0 + rr1);
                #pragma unroll
                for (int nf = 0; nf < 2; ++nf) {
                    int cc = cbase_w + nf*8;
                    float bg0 = __ldg(bgp + cc), bg1 = __ldg(bgp + cc + 1);
                    float bp0 = __ldg(bpp + cc), bp1 = __ldg(bpp + cc + 1);
                    float s00 = 1.f/(1.f + __expf(-(accG[mf][nf][0] + bg0)));
                    float s01 = 1.f/(1.f + __expf(-(accG[mf][nf][1] + bg1)));
                    float s10 = 1.f/(1.f + __expf(-(accG[mf][nf][2] + bg0)));
                    float s11 = 1.f/(1.f + __expf(-(accG[mf][nf][3] + bg1)));
                    stg[cc*68 + rr0]     = (uint32_t)__half_as_ushort(
                        __float2half(m0 * s00 * (accP[mf][nf][0] + bp0)));
                    stg[(cc+1)*68 + rr0] = (uint32_t)__half_as_ushort(
                        __float2half(m0 * s01 * (accP[mf][nf][1] + bp1)));
                    stg[cc*68 + rr1]     = (uint32_t)__half_as_ushort(
                        __float2half(m1 * s10 * (accP[mf][nf][2] + bp0)));
                    stg[(cc+1)*68 + rr1] = (uint32_t)__half_as_ushort(
                        __float2half(m1 * s11 * (accP[mf][nf][3] + bp1)));
                }
            }
            __syncthreads();
            __half* dH = (ph < 2) ? g_ah : g_bh;
            const int cch = (ph & 1) * 64 + (t >> 2);
            const int rrb = (t & 3) * 16;
            size_t off = (size_t)cch * NR + r0 + rrb;
            const uint32_t* sp = stg + (t >> 2) * 68 + rrb;
            __align__(16) unsigned short hb[16];
            #pragma unroll
            for (int i = 0; i < 16; ++i) hb[i] = (unsigned short)(sp[i] & 0xffffu);
            *(uint4*)(dH + off)     = *(uint4*)(hb);
            *(uint4*)(dH + off + 8) = *(uint4*)(hb + 8);
        }
    }
}

// =====================================================================
// Kernel 2 (v4): einsum fp16 single-pass; X written fp16 (unchanged).
// =====================================================================
#define KC     32
#define STR    40
#define TILE_E (128*STR)
#define BUF_E  (2*TILE_E)
#define K2_SMEM (2 * BUF_E * 2)         // 40960

static __device__ __forceinline__ void cp_wait1_k2() {
    asm volatile("cp.async.wait_group 1;" ::: "memory");
}

__global__ void __launch_bounds__(512) k2_einsum_mma() {
    extern __shared__ __half sb[];
    const uint32_t sbase = smem_u32(sb);

    const int t   = threadIdx.x;
    const int lid = t & 31;
    const int w   = t >> 5;
    const int wm  = w >> 2;
    const int wn  = w & 3;
    const int c   = blockIdx.z;
    const int m0  = blockIdx.y * 128;
    const int n0  = blockIdx.x * 128;

    const __half* pAh = g_ah + (size_t)c * NR;
    const __half* pBh = g_bh + (size_t)c * NR;

    const int grow = t >> 2;
    const int gseg = t & 3;
    const size_t gA0 = (size_t)(m0 + grow) * NN + gseg * 8;
    const size_t gB0 = (size_t)(n0 + grow) * NN + gseg * 8;
    const uint32_t sw = (grow * STR + gseg * 8) * 2;

    const int quad = lid >> 3;
    const int l7   = lid & 7;
    uint32_t aoff[2];
    #pragma unroll
    for (int mf = 0; mf < 2; ++mf) {
        int r = wm*32 + mf*16 + (quad & 1)*8 + l7;
        aoff[mf] = (r * STR + (quad >> 1) * 8) * 2;
    }
    uint32_t boff[4];
    #pragma unroll
    for (int nf = 0; nf < 4; ++nf) {
        int r = wn*32 + nf*8 + l7;
        boff[nf] = (r * STR + ((lid >> 3) & 1) * 8) * 2;
    }

    float d[2][4][4];
    #pragma unroll
    for (int mf = 0; mf < 2; ++mf)
        #pragma unroll
        for (int nf = 0; nf < 4; ++nf)
            #pragma unroll
            for (int q = 0; q < 4; ++q) d[mf][nf][q] = 0.f;

    {
        uint32_t b0 = sbase;
        cp16(b0 + 0*TILE_E*2 + sw, pAh + gA0);
        cp16(b0 + 1*TILE_E*2 + sw, pBh + gB0);
        cp_commit();
    }

    for (int ch = 0; ch < 16; ++ch) {
        if (ch < 15) {
            uint32_t bb = sbase + ((ch + 1) & 1) * BUF_E * 2;
            int kk = (ch + 1) * KC;
            cp16(bb + 0*TILE_E*2 + sw, pAh + gA0 + kk);
            cp16(bb + 1*TILE_E*2 + sw, pBh + gB0 + kk);
            cp_commit();
            cp_wait1_k2();
        } else {
            cp_wait0();
        }
        __syncthreads();

        const uint32_t bb = sbase + (ch & 1) * BUF_E * 2;
        const uint32_t bAH = bb;
        const uint32_t bBH = bb + TILE_E*2;

        #pragma unroll
        for (int ks = 0; ks < KC; ks += 16) {
            uint32_t ah[2][4], bh[4][2];
            #pragma unroll
            for (int mf = 0; mf < 2; ++mf) ldmx4(ah[mf], bAH + aoff[mf] + ks*2);
            #pragma unroll
            for (int nf = 0; nf < 4; ++nf) ldmx2(bh[nf], bBH + boff[nf] + ks*2);
            #pragma unroll
            for (int mf = 0; mf < 2; ++mf)
                #pragma unroll
                for (int nf = 0; nf < 4; ++nf)
                    mma16816(d[mf][nf], ah[mf], bh[nf]);
        }
        __syncthreads();
    }

    __half* X = g_x + (size_t)c * NR;
    const int rb = m0 + wm*32 + (lid >> 2);
    const int cb = n0 + wn*32 + (lid & 3) * 2;
    #pragma unroll
    for (int mf = 0; mf < 2; ++mf)
        #pragma unroll
        for (int nf = 0; nf < 4; ++nf) {
            int row = rb + mf*16;
            int col = cb + nf*8;
            *(__half2*)(X + (size_t)row * NN + col) =
                __floats2half2_rn(d[mf][nf][0], d[mf][nf][1]);
            *(__half2*)(X + (size_t)(row + 8) * NN + col) =
                __floats2half2_rn(d[mf][nf][2], d[mf][nf][3]);
        }
}

// =====================================================================
// Kernel 3 (v7): gather x (fp16) -> LN -> @ w_z (fp16 2-PASS: xH*wH + xH*wL)
// -> *gate -> out. AH overlays gather staging; smem 68608 -> 3 CTAs/SM.
// =====================================================================
#define K3_AH 0
#define K3_WH 33792
#define K3_WL 51200
#define K3_SMEM 68608

__global__ void __launch_bounds__(256, 3) k3_mma(
    const float* __restrict__ b_z,
    const float* __restrict__ ln_g, const float* __restrict__ ln_b,
    float* __restrict__ out)
{
    extern __shared__ char smem[];
    const uint32_t sbase = smem_u32(smem);
    float* xS = (float*)smem;                    // [row][c] stride 132 (33792 B)
    const int t   = threadIdx.x;
    const int lid = t & 31;
    const int w   = t >> 5;
    const int wm  = w >> 2;
    const int wn  = w & 3;
    const int r0  = blockIdx.x * 64;
    const int i0  = r0 >> 9;
    const int j0  = r0 & 511;

    // prefetch W chunk 0 (overlaps gather)
    {
        #pragma unroll
        for (int p = 0; p < 4; ++p) {
            int idx = p * 256 + t;
            int n = idx >> 4, seg = idx & 15;
            cp16(sbase + K3_WH + n * 272 + seg * 16,
                 g_wH + (size_t)(640 + n) * 128 + seg * 8);
            cp16(sbase + K3_WL + n * 272 + seg * 16,
                 g_wL + (size_t)(640 + n) * 128 + seg * 8);
        }
        cp_commit();
    }

    // gather x (fp16 c-major) -> fp32 staging
    {
        const int joff = t & 63, part = t >> 6;
        const __half* src = g_x + (size_t)(part*32) * NR + (size_t)i0 * NN + j0 + joff;
        #pragma unroll
        for (int q = 0; q < 32; ++q)
            xS[joff*132 + part*32 + q] = __half2float(src[(size_t)q * NR]);
    }
    __syncthreads();

    // LN into registers (hi only), then overwrite staging with AH
    {
        const int row = t >> 2, qt = t & 3;
        const float* zr = xS + row * 132 + qt * 32;
        float vbuf[32];
        float s = 0.f, s2 = 0.f;
        #pragma unroll
        for (int q = 0; q < 8; ++q) {
            float4 v = *(const float4*)(zr + q * 4);
            vbuf[q*4+0] = v.x; vbuf[q*4+1] = v.y; vbuf[q*4+2] = v.z; vbuf[q*4+3] = v.w;
            s  += v.x + v.y + v.z + v.w;
            s2 += v.x*v.x + v.y*v.y + v.z*v.z + v.w*v.w;
        }
        s  += __shfl_xor_sync(0xffffffffu, s, 1);
        s2 += __shfl_xor_sync(0xffffffffu, s2, 1);
        s  += __shfl_xor_sync(0xffffffffu, s, 2);
        s2 += __shfl_xor_sync(0xffffffffu, s2, 2);
        float mu  = s * (1.0f/128.0f);
        float var = fmaxf(s2 * (1.0f/128.0f) - mu*mu, 0.f);
        float rs  = rsqrtf(var + EPSV);

        __align__(16) __half hb[32];
        #pragma unroll
        for (int j = 0; j < 32; ++j) {
            int c = qt * 32 + j;
            hb[j] = __float2half((vbuf[j] - mu) * rs * __ldg(ln_g + c) + __ldg(ln_b + c));
        }
        __syncthreads();   // all xS reads complete before overlay writes
        __half* aH = (__half*)(smem + K3_AH) + row * ASTR + qt * 32;
        #pragma unroll
        for (int q8 = 0; q8 < 4; ++q8)
            *(uint4*)(aH + q8*8) = *(uint4*)(hb + q8*8);
    }

    const int quad = lid >> 3;
    const int l7   = lid & 7;
    uint32_t aoff[2];
    #pragma unroll
    for (int mf = 0; mf < 2; ++mf) {
        int r = wm*32 + mf*16 + (quad & 1)*8 + l7;
        aoff[mf] = (r * ASTR + (quad >> 1) * 8) * 2;
    }
    const uint32_t boff = ((wn*16 + (quad & 1)*8 + l7) * ASTR + (quad >> 1) * 8) * 2;
    const int rbase = wm*32 + (lid >> 2);
    const int cbase_w = wn*16 + (lid & 3)*2;

    for (int ci = 0; ci < 2; ++ci) {
        __syncthreads();
        if (ci == 1) {
            #pragma unroll
            for (int p = 0; p < 4; ++p) {
                int idx = p * 256 + t;
                int n = idx >> 4, seg = idx & 15;
                cp16(sbase + K3_WH + n * 272 + seg * 16,
                     g_wH + (size_t)(704 + n) * 128 + seg * 8);
                cp16(sbase + K3_WL + n * 272 + seg * 16,
                     g_wL + (size_t)(704 + n) * 128 + seg * 8);
            }
            cp_commit();
        }
        cp_wait0();
        __syncthreads();

        float acc[2][2][4];
        #pragma unroll
        for (int mf = 0; mf < 2; ++mf)
            #pragma unroll
            for (int nf = 0; nf < 2; ++nf)
                #pragma unroll
                for (int q = 0; q < 4; ++q) acc[mf][nf][q] = 0.f;

        #pragma unroll
        for (int ks = 0; ks < 128; ks += 16) {
            uint32_t ah[2][4], bh[2][2], bl[2][2], r4[4];
            ldmx4(ah[0], sbase + K3_AH + aoff[0] + ks*2);
            ldmx4(ah[1], sbase + K3_AH + aoff[1] + ks*2);
            ldmx4(r4, sbase + K3_WH + boff + ks*2);
            bh[0][0] = r4[0]; bh[0][1] = r4[2];
            bh[1][0] = r4[1]; bh[1][1] = r4[3];
            ldmx4(r4, sbase + K3_WL + boff + ks*2);
            bl[0][0] = r4[0]; bl[0][1] = r4[2];
            bl[1][0] = r4[1]; bl[1][1] = r4[3];
            #pragma unroll
            for (int mf = 0; mf < 2; ++mf)
                #pragma unroll
                for (int nf = 0; nf < 2; ++nf)
                    mma16816(acc[mf][nf], ah[mf], bh[nf]);
            #pragma unroll
            for (int mf = 0; mf < 2; ++mf)
                #pragma unroll
                for (int nf = 0; nf < 2; ++nf)
                    mma16816(acc[mf][nf], ah[mf], bl[nf]);
        }

        const int cb2 = ci * 64;
        #pragma unroll
        for (int mf = 0; mf < 2; ++mf) {
            int rr0 = rbase + mf*16, rr1 = rr0 + 8;
            #pragma unroll
            for (int nf = 0; nf < 2; ++nf) {
                int cc = cbase_w + nf*8;
                float b0 = __ldg(b_z + cb2 + cc);
                float b1 = __ldg(b_z + cb2 + cc + 1);
                float2 gg0 = __half22float2(*(const __half2*)(g_gate + (size_t)(r0 + rr0) * CZ + cb2 + cc));
                float2 gg1 = __half22float2(*(const __half2*)(g_gate + (size_t)(r0 + rr1) * CZ + cb2 + cc));
                float2 v0, v1;
                v0.x = (acc[mf][nf][0] + b0) * gg0.x;
                v0.y = (acc[mf][nf][1] + b1) * gg0.y;
                v1.x = (acc[mf][nf][2] + b0) * gg1.x;
                v1.y = (acc[mf][nf][3] + b1) * gg1.y;
                *(float2*)(out + (size_t)(r0 + rr0) * CZ + cb2 + cc) = v0;
                *(float2*)(out + (size_t)(r0 + rr1) * CZ + cb2 + cc) = v1;
            }
        }
    }
}

// =====================================================================
extern "C" void kernel_launch(void* const* d_in, const int* in_sizes, int n_in,
                              void* d_out, int out_size) {
    const float* z       = (const float*)d_in[0];
    const float* mask    = (const float*)d_in[1];
    const float* w_ab_p  = (const float*)d_in[2];
    const float* b_ab_p  = (const float*)d_in[3];
    const float* w_ab_g  = (const float*)d_in[4];
    const float* b_ab_g  = (const float*)d_in[5];
    const float* w_g     = (const float*)d_in[6];
    const float* b_g     = (const float*)d_in[7];
    const float* w_z     = (const float*)d_in[8];
    const float* b_z     = (const float*)d_in[9];
    const float* ln_in_g = (const float*)d_in[10];
    const float* ln_in_b = (const float*)d_in[11];
    const float* ln_out_g= (const float*)d_in[12];
    const float* ln_out_b= (const float*)d_in[13];
    float* out = (float*)d_out;

    cudaFuncSetAttribute(k1_mma,        cudaFuncAttributeMaxDynamicSharedMemorySize, K1_SMEM);
    cudaFuncSetAttribute(k2_einsum_mma, cudaFuncAttributeMaxDynamicSharedMemorySize, K2_SMEM);
    cudaFuncSetAttribute(k3_mma,        cudaFuncAttributeMaxDynamicSharedMemorySize, K3_SMEM);

    k0_wsplit<<<384, 256>>>(w_ab_g, w_ab_p, w_g, w_z);
    k1_mma<<<NR / 64, 256, K1_SMEM>>>(z, mask, b_ab_p, b_ab_g, b_g,
                                      ln_in_g, ln_in_b);
    k2_einsum_mma<<<dim3(4, 4, 128), 512, K2_SMEM>>>();
    k3_mma<<<NR / 64, 256, K3_SMEM>>>(b_z, ln_out_g, ln_out_b, out);
}

// round 17
// speedup vs baseline: 1.2876x; 1.0171x over previous
#include <cuda_runtime.h>
#include <cuda_fp16.h>
#include <math.h>
#include <cstdint>

#define NN   512
#define CZ   128
#define NR   (NN*NN)          // 262144
#define EPSV 1e-5f

// ---------------- scratch (device globals; alloc-free) ----------------
__device__ __half g_ah[(size_t)CZ * NR];   // a hi [c][i][k]
__device__ __half g_bh[(size_t)CZ * NR];   // b hi [c][j][k]
__device__ __half g_gate[(size_t)NR * CZ]; // gate[r][c]  (fp16)
__device__ __half g_x[(size_t)CZ * NR];    // x[c][i][j]  (fp16, L2-resident)
__device__ __half g_wH[768 * 128];         // packed weights hi [n][k]

static __device__ __forceinline__ uint32_t smem_u32(const void* p) {
    return (uint32_t)__cvta_generic_to_shared(p);
}
static __device__ __forceinline__ void cp16(uint32_t dst, const void* src) {
    asm volatile("cp.async.cg.shared.global [%0], [%1], 16;" :: "r"(dst), "l"(src));
}
static __device__ __forceinline__ void cp_commit() {
    asm volatile("cp.async.commit_group;" ::: "memory");
}
static __device__ __forceinline__ void cp_wait0() {
    asm volatile("cp.async.wait_group 0;" ::: "memory");
}
static __device__ __forceinline__ void ldmx4(uint32_t* r, uint32_t addr) {
    asm volatile("ldmatrix.sync.aligned.m8n8.x4.shared.b16 {%0,%1,%2,%3}, [%4];"
                 : "=r"(r[0]), "=r"(r[1]), "=r"(r[2]), "=r"(r[3]) : "r"(addr));
}
static __device__ __forceinline__ void ldmx2(uint32_t* r, uint32_t addr) {
    asm volatile("ldmatrix.sync.aligned.m8n8.x2.shared.b16 {%0,%1}, [%2];"
                 : "=r"(r[0]), "=r"(r[1]) : "r"(addr));
}
static __device__ __forceinline__ void mma16816(float* d, const uint32_t* a, const uint32_t* b) {
    asm volatile("mma.sync.aligned.m16n8k16.row.col.f32.f16.f16.f32 "
                 "{%0,%1,%2,%3}, {%4,%5,%6,%7}, {%8,%9}, {%0,%1,%2,%3};"
                 : "+f"(d[0]), "+f"(d[1]), "+f"(d[2]), "+f"(d[3])
                 : "r"(a[0]), "r"(a[1]), "r"(a[2]), "r"(a[3]), "r"(b[0]), "r"(b[1]));
}

// =====================================================================
// Kernel 0: round weights to fp16 hi, transposed to [n][k].
// n: 0-255 = w_ab_g, 256-511 = w_ab_p, 512-639 = w_g, 640-767 = w_z
// =====================================================================
__global__ void __launch_bounds__(256) k0_wsplit(
    const float* __restrict__ w_ab_g, const float* __restrict__ w_ab_p,
    const float* __restrict__ w_g,   const float* __restrict__ w_z)
{
    int idx = blockIdx.x * 256 + threadIdx.x;   // 384 blocks
    if (idx >= 768 * 128) return;
    int n = idx >> 7, k = idx & 127;
    float v;
    if (n < 256)      v = w_ab_g[k * 256 + n];
    else if (n < 512) v = w_ab_p[k * 256 + (n - 256)];
    else if (n < 640) v = w_g[k * 128 + (n - 512)];
    else              v = w_z[k * 128 + (n - 640)];
    g_wH[idx] = __float2half(v);
}

// =====================================================================
// Kernel 1 (v7): LN(z) + projections, fp16 single-pass, G/P paired.
// SINGLE W buffer, smem 52224 -> 3 CTAs/SM. (unchanged from R15)
// =====================================================================
#define ASTR   136
#define OFF_AH 0                       // 17408 B
#define OFF_WG 17408                   // 17408 B (Wg chunk; also P staging)
#define OFF_WP 34816                   // 17408 B (Wp chunk)
#define K1_SMEM 52224

__global__ void __launch_bounds__(256, 3) k1_mma(
    const float* __restrict__ z, const float* __restrict__ mask,
    const float* __restrict__ b_ab_p, const float* __restrict__ b_ab_g,
    const float* __restrict__ b_g,
    const float* __restrict__ ln_g,  const float* __restrict__ ln_b)
{
    extern __shared__ char smem[];
    const uint32_t sbase = smem_u32(smem);
    const int t   = threadIdx.x;
    const int lid = t & 31;
    const int w   = t >> 5;
    const int wm  = w >> 2;
    const int wn  = w & 3;
    const int r0  = blockIdx.x * 64;

    {
        #pragma unroll
        for (int p = 0; p < 4; ++p) {
            int idx = p * 256 + t;
            int n = idx >> 4, seg = idx & 15;
            cp16(sbase + OFF_WG + n * 272 + seg * 16,
                 g_wH + (size_t)n * 128 + seg * 8);
            cp16(sbase + OFF_WP + n * 272 + seg * 16,
                 g_wH + (size_t)(256 + n) * 128 + seg * 8);
        }
        cp_commit();
    }

    {
        const int row = t >> 2, qt = t & 3;
        const float4* zr = (const float4*)(z + (size_t)(r0 + row) * CZ + qt * 32);
        float4 v[8];
        #pragma unroll
        for (int q = 0; q < 8; ++q) v[q] = __ldg(zr + q);
        float s = 0.f, s2 = 0.f;
        #pragma unroll
        for (int q = 0; q < 8; ++q) {
            s  += v[q].x + v[q].y + v[q].z + v[q].w;
            s2 += v[q].x*v[q].x + v[q].y*v[q].y + v[q].z*v[q].z + v[q].w*v[q].w;
        }
        s  += __shfl_xor_sync(0xffffffffu, s, 1);
        s2 += __shfl_xor_sync(0xffffffffu, s2, 1);
        s  += __shfl_xor_sync(0xffffffffu, s, 2);
        s2 += __shfl_xor_sync(0xffffffffu, s2, 2);
        float mu  = s * (1.0f/128.0f);
        float var = fmaxf(s2 * (1.0f/128.0f) - mu*mu, 0.f);
        float rs  = rsqrtf(var + EPSV);

        __half* aH = (__half*)(smem + OFF_AH) + row * ASTR + qt * 32;
        #pragma unroll
        for (int q8 = 0; q8 < 4; ++q8) {
            const float vv[8] = {v[q8*2].x, v[q8*2].y, v[q8*2].z, v[q8*2].w,
                                 v[q8*2+1].x, v[q8*2+1].y, v[q8*2+1].z, v[q8*2+1].w};
            __align__(16) __half hb[8];
            #pragma unroll
            for (int j = 0; j < 8; ++j) {
                int c = qt * 32 + q8 * 8 + j;
                hb[j] = __float2half((vv[j] - mu) * rs * __ldg(ln_g + c) + __ldg(ln_b + c));
            }
            *(uint4*)(aH + q8*8) = *(uint4*)hb;
        }
    }

    const int quad = lid >> 3;
    const int l7   = lid & 7;
    uint32_t aoff[2];
    #pragma unroll
    for (int mf = 0; mf < 2; ++mf) {
        int r = wm*32 + mf*16 + (quad & 1)*8 + l7;
        aoff[mf] = (r * ASTR + (quad >> 1) * 8) * 2;
    }
    const uint32_t boff = ((wn*16 + (quad & 1)*8 + l7) * ASTR + (quad >> 1) * 8) * 2;
    const int rbase = wm*32 + (lid >> 2);
    const int cbase_w = wn*16 + (lid & 3)*2;

    for (int ph = 0; ph < 5; ++ph) {
        __syncthreads();
        if (ph > 0) {
            const int t0 = (ph < 4) ? ph * 64 : 512;
            const int t1 = (ph < 4) ? 256 + ph * 64 : 576;
            #pragma unroll
            for (int p = 0; p < 4; ++p) {
                int idx = p * 256 + t;
                int n = idx >> 4, seg = idx & 15;
                cp16(sbase + OFF_WG + n * 272 + seg * 16,
                     g_wH + (size_t)(t0 + n) * 128 + seg * 8);
                cp16(sbase + OFF_WP + n * 272 + seg * 16,
                     g_wH + (size_t)(t1 + n) * 128 + seg * 8);
            }
            cp_commit();
        }
        cp_wait0();
        __syncthreads();

        float accG[2][2][4], accP[2][2][4];
        #pragma unroll
        for (int mf = 0; mf < 2; ++mf)
            #pragma unroll
            for (int nf = 0; nf < 2; ++nf)
                #pragma unroll
                for (int q = 0; q < 4; ++q) { accG[mf][nf][q] = 0.f; accP[mf][nf][q] = 0.f; }

        #pragma unroll
        for (int ks = 0; ks < 128; ks += 16) {
            uint32_t ah[2][4], bg2[2][2], bp2[2][2], r4[4];
            ldmx4(ah[0], sbase + OFF_AH + aoff[0] + ks*2);
            ldmx4(ah[1], sbase + OFF_AH + aoff[1] + ks*2);
            ldmx4(r4, sbase + OFF_WG + boff + ks*2);
            bg2[0][0] = r4[0]; bg2[0][1] = r4[2];
            bg2[1][0] = r4[1]; bg2[1][1] = r4[3];
            ldmx4(r4, sbase + OFF_WP + boff + ks*2);
            bp2[0][0] = r4[0]; bp2[0][1] = r4[2];
            bp2[1][0] = r4[1]; bp2[1][1] = r4[3];
            #pragma unroll
            for (int mf = 0; mf < 2; ++mf)
                #pragma unroll
                for (int nf = 0; nf < 2; ++nf)
                    mma16816(accG[mf][nf], ah[mf], bg2[nf]);
            #pragma unroll
            for (int mf = 0; mf < 2; ++mf)
                #pragma unroll
                for (int nf = 0; nf < 2; ++nf)
                    mma16816(accP[mf][nf], ah[mf], bp2[nf]);
        }

        if (ph == 4) {
            #pragma unroll
            for (int mf = 0; mf < 2; ++mf) {
                int rr0 = rbase + mf*16, rr1 = rr0 + 8;
                #pragma unroll
                for (int nf = 0; nf < 2; ++nf) {
                    int cc = cbase_w + nf*8;
                    float g0 = __ldg(b_g + cc),       g1 = __ldg(b_g + cc + 1);
                    float g2 = __ldg(b_g + 64 + cc),  g3 = __ldg(b_g + 64 + cc + 1);
                    __half2 hA0, hA1, hB0, hB1;
                    hA0.x = __float2half(1.f/(1.f + __expf(-(accG[mf][nf][0] + g0))));
                    hA0.y = __float2half(1.f/(1.f + __expf(-(accG[mf][nf][1] + g1))));
                    hA1.x = __float2half(1.f/(1.f + __expf(-(accG[mf][nf][2] + g0))));
                    hA1.y = __float2half(1.f/(1.f + __expf(-(accG[mf][nf][3] + g1))));
                    hB0.x = __float2half(1.f/(1.f + __expf(-(accP[mf][nf][0] + g2))));
                    hB0.y = __float2half(1.f/(1.f + __expf(-(accP[mf][nf][1] + g3))));
                    hB1.x = __float2half(1.f/(1.f + __expf(-(accP[mf][nf][2] + g2))));
                    hB1.y = __float2half(1.f/(1.f + __expf(-(accP[mf][nf][3] + g3))));
                    *(__half2*)(g_gate + (size_t)(r0 + rr0) * CZ + cc)      = hA0;
                    *(__half2*)(g_gate + (size_t)(r0 + rr1) * CZ + cc)      = hA1;
                    *(__half2*)(g_gate + (size_t)(r0 + rr0) * CZ + 64 + cc) = hB0;
                    *(__half2*)(g_gate + (size_t)(r0 + rr1) * CZ + 64 + cc) = hB1;
                }
            }
        } else {
            const float* bgp = b_ab_g + ph * 64;
            const float* bpp = b_ab_p + ph * 64;
            __syncthreads();
            uint32_t* stg = (uint32_t*)(smem + OFF_WG);
            #pragma unroll
            for (int mf = 0; mf < 2; ++mf) {
                int rr0 = rbase + mf*16, rr1 = rr0 + 8;
                float m0 = __ldg(mask + r0 + rr0);
                float m1 = __ldg(mask + r0 + rr1);
                #pragma unroll
                for (int nf = 0; nf < 2; ++nf) {
                    int cc = cbase_w + nf*8;
                    float bg0 = __ldg(bgp + cc), bg1 = __ldg(bgp + cc + 1);
                    float bp0 = __ldg(bpp + cc), bp1 = __ldg(bpp + cc + 1);
                    float s00 = 1.f/(1.f + __expf(-(accG[mf][nf][0] + bg0)));
                    float s01 = 1.f/(1.f + __expf(-(accG[mf][nf][1] + bg1)));
                    float s10 = 1.f/(1.f + __expf(-(accG[mf][nf][2] + bg0)));
                    float s11 = 1.f/(1.f + __expf(-(accG[mf][nf][3] + bg1)));
                    stg[cc*68 + rr0]     = (uint32_t)__half_as_ushort(
                        __float2half(m0 * s00 * (accP[mf][nf][0] + bp0)));
                    stg[(cc+1)*68 + rr0] = (uint32_t)__half_as_ushort(
                        __float2half(m0 * s01 * (accP[mf][nf][1] + bp1)));
                    stg[cc*68 + rr1]     = (uint32_t)__half_as_ushort(
                        __float2half(m1 * s10 * (accP[mf][nf][2] + bp0)));
                    stg[(cc+1)*68 + rr1] = (uint32_t)__half_as_ushort(
                        __float2half(m1 * s11 * (accP[mf][nf][3] + bp1)));
                }
            }
            __syncthreads();
            __half* dH = (ph < 2) ? g_ah : g_bh;
            const int cch = (ph & 1) * 64 + (t >> 2);
            const int rrb = (t & 3) * 16;
            size_t off = (size_t)cch * NR + r0 + rrb;
            const uint32_t* sp = stg + (t >> 2) * 68 + rrb;
            __align__(16) unsigned short hb[16];
            #pragma unroll
            for (int i = 0; i < 16; ++i) hb[i] = (unsigned short)(sp[i] & 0xffffu);
            *(uint4*)(dH + off)     = *(uint4*)(hb);
            *(uint4*)(dH + off + 8) = *(uint4*)(hb + 8);
        }
    }
}

// =====================================================================
// Kernel 2 (v4): einsum fp16 single-pass; X written fp16 (unchanged).
// =====================================================================
#define KC     32
#define STR    40
#define TILE_E (128*STR)
#define BUF_E  (2*TILE_E)
#define K2_SMEM (2 * BUF_E * 2)         // 40960

static __device__ __forceinline__ void cp_wait1_k2() {
    asm volatile("cp.async.wait_group 1;" ::: "memory");
}

__global__ void __launch_bounds__(512) k2_einsum_mma() {
    extern __shared__ __half sb[];
    const uint32_t sbase = smem_u32(sb);

    const int t   = threadIdx.x;
    const int lid = t & 31;
    const int w   = t >> 5;
    const int wm  = w >> 2;
    const int wn  = w & 3;
    const int c   = blockIdx.z;
    const int m0  = blockIdx.y * 128;
    const int n0  = blockIdx.x * 128;

    const __half* pAh = g_ah + (size_t)c * NR;
    const __half* pBh = g_bh + (size_t)c * NR;

    const int grow = t >> 2;
    const int gseg = t & 3;
    const size_t gA0 = (size_t)(m0 + grow) * NN + gseg * 8;
    const size_t gB0 = (size_t)(n0 + grow) * NN + gseg * 8;
    const uint32_t sw = (grow * STR + gseg * 8) * 2;

    const int quad = lid >> 3;
    const int l7   = lid & 7;
    uint32_t aoff[2];
    #pragma unroll
    for (int mf = 0; mf < 2; ++mf) {
        int r = wm*32 + mf*16 + (quad & 1)*8 + l7;
        aoff[mf] = (r * STR + (quad >> 1) * 8) * 2;
    }
    uint32_t boff[4];
    #pragma unroll
    for (int nf = 0; nf < 4; ++nf) {
        int r = wn*32 + nf*8 + l7;
        boff[nf] = (r * STR + ((lid >> 3) & 1) * 8) * 2;
    }

    float d[2][4][4];
    #pragma unroll
    for (int mf = 0; mf < 2; ++mf)
        #pragma unroll
        for (int nf = 0; nf < 4; ++nf)
            #pragma unroll
            for (int q = 0; q < 4; ++q) d[mf][nf][q] = 0.f;

    {
        uint32_t b0 = sbase;
        cp16(b0 + 0*TILE_E*2 + sw, pAh + gA0);
        cp16(b0 + 1*TILE_E*2 + sw, pBh + gB0);
        cp_commit();
    }

    for (int ch = 0; ch < 16; ++ch) {
        if (ch < 15) {
            uint32_t bb = sbase + ((ch + 1) & 1) * BUF_E * 2;
            int kk = (ch + 1) * KC;
            cp16(bb + 0*TILE_E*2 + sw, pAh + gA0 + kk);
            cp16(bb + 1*TILE_E*2 + sw, pBh + gB0 + kk);
            cp_commit();
            cp_wait1_k2();
        } else {
            cp_wait0();
        }
        __syncthreads();

        const uint32_t bb = sbase + (ch & 1) * BUF_E * 2;
        const uint32_t bAH = bb;
        const uint32_t bBH = bb + TILE_E*2;

        #pragma unroll
        for (int ks = 0; ks < KC; ks += 16) {
            uint32_t ah[2][4], bh[4][2];
            #pragma unroll
            for (int mf = 0; mf < 2; ++mf) ldmx4(ah[mf], bAH + aoff[mf] + ks*2);
            #pragma unroll
            for (int nf = 0; nf < 4; ++nf) ldmx2(bh[nf], bBH + boff[nf] + ks*2);
            #pragma unroll
            for (int mf = 0; mf < 2; ++mf)
                #pragma unroll
                for (int nf = 0; nf < 4; ++nf)
                    mma16816(d[mf][nf], ah[mf], bh[nf]);
        }
        __syncthreads();
    }

    __half* X = g_x + (size_t)c * NR;
    const int rb = m0 + wm*32 + (lid >> 2);
    const int cb = n0 + wn*32 + (lid & 3) * 2;
    #pragma unroll
    for (int mf = 0; mf < 2; ++mf)
        #pragma unroll
        for (int nf = 0; nf < 4; ++nf) {
            int row = rb + mf*16;
            int col = cb + nf*8;
            *(__half2*)(X + (size_t)row * NN + col) =
                __floats2half2_rn(d[mf][nf][0], d[mf][nf][1]);
            *(__half2*)(X + (size_t)(row + 8) * NN + col) =
                __floats2half2_rn(d[mf][nf][2], d[mf][nf][3]);
        }
}

// =====================================================================
// Kernel 3 (v8b): gather x (fp16) -> LN -> @ w_z (fp16 SINGLE-pass) ->
// *gate -> out. Staging stride 132 (16B-aligned); AH overlays staging;
// smem 51200 -> 3 CTAs/SM.
// =====================================================================
#define XSTR   132
#define K3_AH  0
#define K3_WH  33792                    // 64*132*4 = 33792
#define K3_SMEM 51200

__global__ void __launch_bounds__(256, 3) k3_mma(
    const float* __restrict__ b_z,
    const float* __restrict__ ln_g, const float* __restrict__ ln_b,
    float* __restrict__ out)
{
    extern __shared__ char smem[];
    const uint32_t sbase = smem_u32(smem);
    float* xS = (float*)smem;                    // [row][c] stride XSTR
    const int t   = threadIdx.x;
    const int lid = t & 31;
    const int w   = t >> 5;
    const int wm  = w >> 2;
    const int wn  = w & 3;
    const int r0  = blockIdx.x * 64;
    const int i0  = r0 >> 9;
    const int j0  = r0 & 511;

    // prefetch W chunk 0 (overlaps gather)
    {
        #pragma unroll
        for (int p = 0; p < 4; ++p) {
            int idx = p * 256 + t;
            int n = idx >> 4, seg = idx & 15;
            cp16(sbase + K3_WH + n * 272 + seg * 16,
                 g_wH + (size_t)(640 + n) * 128 + seg * 8);
        }
        cp_commit();
    }

    // gather x (fp16 c-major) -> fp32 staging
    {
        const int joff = t & 63, part = t >> 6;
        const __half* src = g_x + (size_t)(part*32) * NR + (size_t)i0 * NN + j0 + joff;
        #pragma unroll
        for (int q = 0; q < 32; ++q)
            xS[joff*XSTR + part*32 + q] = __half2float(src[(size_t)q * NR]);
    }
    __syncthreads();

    // LN into registers (hi only), then overwrite staging with AH
    {
        const int row = t >> 2, qt = t & 3;
        const float* zr = xS + row * XSTR + qt * 32;
        float vbuf[32];
        float s = 0.f, s2 = 0.f;
        #pragma unroll
        for (int q = 0; q < 8; ++q) {
            float4 v = *(const float4*)(zr + q * 4);
            vbuf[q*4+0] = v.x; vbuf[q*4+1] = v.y; vbuf[q*4+2] = v.z; vbuf[q*4+3] = v.w;
            s  += v.x + v.y + v.z + v.w;
            s2 += v.x*v.x + v.y*v.y + v.z*v.z + v.w*v.w;
        }
        s  += __shfl_xor_sync(0xffffffffu, s, 1);
        s2 += __shfl_xor_sync(0xffffffffu, s2, 1);
        s  += __shfl_xor_sync(0xffffffffu, s, 2);
        s2 += __shfl_xor_sync(0xffffffffu, s2, 2);
        float mu  = s * (1.0f/128.0f);
        float var = fmaxf(s2 * (1.0f/128.0f) - mu*mu, 0.f);
        float rs  = rsqrtf(var + EPSV);

        __align__(16) __half hb[32];
        #pragma unroll
        for (int j = 0; j < 32; ++j) {
            int c = qt * 32 + j;
            hb[j] = __float2half((vbuf[j] - mu) * rs * __ldg(ln_g + c) + __ldg(ln_b + c));
        }
        __syncthreads();   // all xS reads complete before overlay writes
        __half* aH = (__half*)(smem + K3_AH) + row * ASTR + qt * 32;
        #pragma unroll
        for (int q8 = 0; q8 < 4; ++q8)
            *(uint4*)(aH + q8*8) = *(uint4*)(hb + q8*8);
    }

    const int quad = lid >> 3;
    const int l7   = lid & 7;
    uint32_t aoff[2];
    #pragma unroll
    for (int mf = 0; mf < 2; ++mf) {
        int r = wm*32 + mf*16 + (quad & 1)*8 + l7;
        aoff[mf] = (r * ASTR + (quad >> 1) * 8) * 2;
    }
    const uint32_t boff = ((wn*16 + (quad & 1)*8 + l7) * ASTR + (quad >> 1) * 8) * 2;
    const int rbase = wm*32 + (lid >> 2);
    const int cbase_w = wn*16 + (lid & 3)*2;

    for (int ci = 0; ci < 2; ++ci) {
        __syncthreads();
        if (ci == 1) {
            #pragma unroll
            for (int p = 0; p < 4; ++p) {
                int idx = p * 256 + t;
                int n = idx >> 4, seg = idx & 15;
                cp16(sbase + K3_WH + n * 272 + seg * 16,
                     g_wH + (size_t)(704 + n) * 128 + seg * 8);
            }
            cp_commit();
        }
        cp_wait0();
        __syncthreads();

        float acc[2][2][4];
        #pragma unroll
        for (int mf = 0; mf < 2; ++mf)
            #pragma unroll
            for (int nf = 0; nf < 2; ++nf)
                #pragma unroll
                for (int q = 0; q < 4; ++q) acc[mf][nf][q] = 0.f;

        #pragma unroll
        for (int ks = 0; ks < 128; ks += 16) {
            uint32_t ah[2][4], bh[2][2], r4[4];
            ldmx4(ah[0], sbase + K3_AH + aoff[0] + ks*2);
            ldmx4(ah[1], sbase + K3_AH + aoff[1] + ks*2);
            ldmx4(r4, sbase + K3_WH + boff + ks*2);
            bh[0][0] = r4[0]; bh[0][1] = r4[2];
            bh[1][0] = r4[1]; bh[1][1] = r4[3];
            #pragma unroll
            for (int mf = 0; mf < 2; ++mf)
                #pragma unroll
                for (int nf = 0; nf < 2; ++nf)
                    mma16816(acc[mf][nf], ah[mf], bh[nf]);
        }

        const int cb2 = ci * 64;
        #pragma unroll
        for (int mf = 0; mf < 2; ++mf) {
            int rr0 = rbase + mf*16, rr1 = rr0 + 8;
            #pragma unroll
            for (int nf = 0; nf < 2; ++nf) {
                int cc = cbase_w + nf*8;
                float b0 = __ldg(b_z + cb2 + cc);
                float b1 = __ldg(b_z + cb2 + cc + 1);
                float2 gg0 = __half22float2(*(const __half2*)(g_gate + (size_t)(r0 + rr0) * CZ + cb2 + cc));
                float2 gg1 = __half22float2(*(const __half2*)(g_gate + (size_t)(r0 + rr1) * CZ + cb2 + cc));
                float2 v0, v1;
                v0.x = (acc[mf][nf][0] + b0) * gg0.x;
                v0.y = (acc[mf][nf][1] + b1) * gg0.y;
                v1.x = (acc[mf][nf][2] + b0) * gg1.x;
                v1.y = (acc[mf][nf][3] + b1) * gg1.y;
                *(float2*)(out + (size_t)(r0 + rr0) * CZ + cb2 + cc) = v0;
                *(float2*)(out + (size_t)(r0 + rr1) * CZ + cb2 + cc) = v1;
            }
        }
    }
}

// =====================================================================
extern "C" void kernel_launch(void* const* d_in, const int* in_sizes, int n_in,
                              void* d_out, int out_size) {
    const float* z       = (const float*)d_in[0];
    const float* mask    = (const float*)d_in[1];
    const float* w_ab_p  = (const float*)d_in[2];
    const float* b_ab_p  = (const float*)d_in[3];
    const float* w_ab_g  = (const float*)d_in[4];
    const float* b_ab_g  = (const float*)d_in[5];
    const float* w_g     = (const float*)d_in[6];
    const float* b_g     = (const float*)d_in[7];
    const float* w_z     = (const float*)d_in[8];
    const float* b_z     = (const float*)d_in[9];
    const float* ln_in_g = (const float*)d_in[10];
    const float* ln_in_b = (const float*)d_in[11];
    const float* ln_out_g= (const float*)d_in[12];
    const float* ln_out_b= (const float*)d_in[13];
    float* out = (float*)d_out;

    cudaFuncSetAttribute(k1_mma,        cudaFuncAttributeMaxDynamicSharedMemorySize, K1_SMEM);
    cudaFuncSetAttribute(k2_einsum_mma, cudaFuncAttributeMaxDynamicSharedMemorySize, K2_SMEM);
    cudaFuncSetAttribute(k3_mma,        cudaFuncAttributeMaxDynamicSharedMemorySize, K3_SMEM);

    k0_wsplit<<<384, 256>>>(w_ab_g, w_ab_p, w_g, w_z);
    k1_mma<<<NR / 64, 256, K1_SMEM>>>(z, mask, b_ab_p, b_ab_g, b_g,
                                      ln_in_g, ln_in_b);
    k2_einsum_mma<<<dim3(4, 4, 128), 512, K2_SMEM>>>();
    k3_mma<<<NR / 64, 256, K3_SMEM>>>(b_z, ln_out_g, ln_out_b, out);
}